// round 12
// baseline (speedup 1.0000x reference)
#include <cuda_runtime.h>
#include <cuda_bf16.h>
#include <math.h>

#define BB   2
#define LL   9216
#define HH   96
#define WIMG 96
#define D2C  192
#define D4C  768
#define NST  16
#define NCH  96
#define CLEN 96

typedef unsigned long long ull;

// ---------------- scratch (device globals; no allocation) ----------------
__device__ float g_xz   [BB*LL*384];       // (b,l,384): xx | z
__device__ float g_xc   [BB*LL*D2C];       // conv+silu output, (b,l,192)
__device__ float g_xdp  [2][BB*LL*40];     // k3a partials (per d-half)
__device__ float g_y    [BB*LL*D4C];       // scan outputs
__device__ float g_gT   [BB*D2C*LL];       // gated values, d-major transposed
__device__ float g_chH  [BB*NCH*D4C*NST];  // chunk local end-state
__device__ float g_chP  [BB*NCH*D4C*NST];  // chunk a-products
__device__ float g_h0   [BB*NCH*D4C*NST];  // per-chunk initial states
__device__ float g_A    [D4C*NST];         // -exp(A_log)
__device__ float g_Wf   [D2C*40];          // folded forward W_x (padded)
__device__ float g_Wb   [D2C*40];          // folded backward W_x (padded)

// ---------------- packed f32x2 helpers ----------------
__device__ __forceinline__ ull pk2(float lo, float hi) {
    ull r;
    asm("mov.b64 %0, {%1, %2};" : "=l"(r) : "f"(lo), "f"(hi));
    return r;
}
__device__ __forceinline__ float2 upk2(ull v) {
    float2 r;
    asm("mov.b64 {%0, %1}, %2;" : "=f"(r.x), "=f"(r.y) : "l"(v));
    return r;
}
__device__ __forceinline__ ull f2mul(ull a, ull b) {
    ull d;
    asm("mul.rn.f32x2 %0, %1, %2;" : "=l"(d) : "l"(a), "l"(b));
    return d;
}
__device__ __forceinline__ ull f2fma(ull a, ull b, ull c) {
    ull d;
    asm("fma.rn.f32x2 %0, %1, %2, %3;" : "=l"(d) : "l"(a), "l"(b), "l"(c));
    return d;
}

// log-depth ladder: av[k] = (e1^(2k+1), e1^(2k+2)), k=0..7
__device__ __forceinline__ void av_ladder(float e1, ull* av) {
    float e2 = e1*e1;
    float e4 = e2*e2;
    float e8 = e4*e4;
    ull p2 = pk2(e2, e2), p4 = pk2(e4, e4), p8 = pk2(e8, e8);
    av[0] = pk2(e1, e2);
    av[1] = f2mul(av[0], p2);
    av[2] = f2mul(av[0], p4);
    av[3] = f2mul(av[1], p4);
    av[4] = f2mul(av[0], p8);
    av[5] = f2mul(av[1], p8);
    av[6] = f2mul(av[2], p8);
    av[7] = f2mul(av[3], p8);
}

// ---------------- K1: in-projection GEMM + folded prep ----------------
__global__ void k1_inproj(const float* __restrict__ x,
                          const float* __restrict__ W_in,
                          const float* __restrict__ b_in,
                          const float* __restrict__ A_log,
                          const float* __restrict__ W_x) {
    __shared__ float sXd[24*64];     // duplicated pixels: (x,x) pairs
    __shared__ float sW [24*384];
    int tid = threadIdx.x;
    int b  = blockIdx.y;
    int l0 = blockIdx.x*32;

    // folded prep (blocks of b==0 only; no consumer until k3a/k4a)
    if (b == 0) {
        int i = blockIdx.x*256 + tid;
        if (i < D4C*NST) g_A[i] = -expf(A_log[i]);
        if (i < D2C*40) {
            int d = i/40, j = i%40;
            float vf = 0.f, vb = 0.f;
            if (j < 38) {
                vf = W_x[d*38+j]       + W_x[(d+192)*38+j];
                vb = W_x[(d+384)*38+j] + W_x[(d+576)*38+j];
            }
            g_Wf[i] = vf;
            g_Wb[i] = vb;
        }
    }

    int eg = tid & 31;
    int jq = tid >> 5;
    ull acc[6][4];
#pragma unroll
    for (int k = 0; k < 6; k++)
#pragma unroll
        for (int p = 0; p < 4; p++) acc[k][p] = 0ull;

    for (int c0 = 0; c0 < 96; c0 += 24) {
        __syncthreads();
        for (int i = tid; i < 24*32; i += 256) {
            int c = i >> 5, j = i & 31;
            float v = x[(b*96 + c0 + c)*LL + l0 + j];
            ((float2*)sXd)[c*32 + j] = make_float2(v, v);
        }
        for (int i = tid; i < 24*384; i += 256)
            sW[i] = W_in[c0*384 + i];
        __syncthreads();
#pragma unroll 4
        for (int cc = 0; cc < 24; cc++) {
            ull xd[4];
#pragma unroll
            for (int p = 0; p < 4; p++)
                xd[p] = ((const ull*)sXd)[cc*32 + jq*4 + p];
            const ull* wrow = (const ull*)(sW + cc*384);
#pragma unroll
            for (int k = 0; k < 6; k++) {
                ull wk = wrow[eg + 32*k];
#pragma unroll
                for (int p = 0; p < 4; p++)
                    acc[k][p] = f2fma(xd[p], wk, acc[k][p]);
            }
        }
    }
    int lbase = l0 + jq*4;
#pragma unroll
    for (int k = 0; k < 6; k++) {
        int e0 = 2*(eg + 32*k);
        float2 bb = *(const float2*)(b_in + e0);
#pragma unroll
        for (int p = 0; p < 4; p++) {
            float2 v = upk2(acc[k][p]);
            v.x += bb.x; v.y += bb.y;
            *(float2*)(g_xz + (size_t)(b*LL + lbase + p)*384 + e0) = v;
        }
    }
}

// ---------------- K2: depthwise 3x3 conv + bias + SiLU (4 px/thread) ----------------
__global__ void k2_conv(const float* __restrict__ w_dw, const float* __restrict__ b_dw) {
    int t = blockIdx.x*256 + threadIdx.x;
    int d = t % 192;
    int rem = t / 192;
    int w4 = rem % 24;
    int rem2 = rem / 24;
    int h = rem2 % HH;
    int b = rem2 / HH;
    int w0 = w4*4;

    float wt[9];
#pragma unroll
    for (int k = 0; k < 9; k++) wt[k] = w_dw[d*9 + k];
    float bias = b_dw[d];
    float acc[4] = {bias, bias, bias, bias};

#pragma unroll
    for (int kh = -1; kh <= 1; kh++) {
        int hh = h + kh;
        if (hh < 0 || hh >= HH) continue;
        float v[6];
#pragma unroll
        for (int c = 0; c < 6; c++) {
            int ww = w0 + c - 1;
            v[c] = (ww >= 0 && ww < WIMG)
                 ? g_xz[(size_t)(b*LL + hh*WIMG + ww)*384 + d] : 0.f;
        }
#pragma unroll
        for (int p = 0; p < 4; p++)
#pragma unroll
            for (int kw = 0; kw < 3; kw++)
                acc[p] = fmaf(v[p+kw], wt[(kh+1)*3 + kw], acc[p]);
    }
#pragma unroll
    for (int p = 0; p < 4; p++) {
        float a = acc[p];
        g_xc[(size_t)(b*LL + h*WIMG + w0 + p)*192 + d] = __fdividef(a, 1.f + __expf(-a));
    }
}

// ---------------- K3a: x_dbl partials, chunked W staging (round-6, DO NOT TOUCH) ----------------
__global__ void k3a_xdbl() {
    __shared__ float sXf[32*132];
    __shared__ float sXb[32*132];
    __shared__ float sWf[32*40];
    __shared__ float sWb[32*40];
    int tid = threadIdx.x;
    int b  = blockIdx.z;
    int dh = blockIdx.y;
    int l0 = blockIdx.x*128;
    int d0 = dh*96;
    int pg = tid >> 3;
    int jg = tid & 7;

    float acc[4][5];
#pragma unroll
    for (int p = 0; p < 4; p++)
#pragma unroll
        for (int q = 0; q < 5; q++) acc[p][q] = 0.f;

    for (int ch = 0; ch < 3; ch++) {
        __syncthreads();
        int db = d0 + ch*32;
        for (int i = tid; i < 128*32; i += 256) {
            int pix = i >> 5, dd = i & 31;
            int l = l0 + pix;
            sXf[dd*132 + pix] = g_xc[(size_t)(b*LL + l)*192 + db + dd];
            sXb[dd*132 + pix] = g_xc[(size_t)(b*LL + (LL-1-l))*192 + db + dd];
        }
        for (int i = tid; i < 32*40; i += 256) {
            sWf[i] = g_Wf[db*40 + i];
            sWb[i] = g_Wb[db*40 + i];
        }
        __syncthreads();
#pragma unroll 4
        for (int dd = 0; dd < 32; dd++) {
            float4 xf4 = *(const float4*)(sXf + dd*132 + pg*4);
            float4 xb4 = *(const float4*)(sXb + dd*132 + pg*4);
            float xf[4] = {xf4.x, xf4.y, xf4.z, xf4.w};
            float xb[4] = {xb4.x, xb4.y, xb4.z, xb4.w};
            int wrow = dd*40 + jg*5;
            float wf[5], wb[5];
#pragma unroll
            for (int q = 0; q < 5; q++) { wf[q] = sWf[wrow+q]; wb[q] = sWb[wrow+q]; }
#pragma unroll
            for (int p = 0; p < 4; p++)
#pragma unroll
                for (int q = 0; q < 5; q++)
                    acc[p][q] += xf[p]*wf[q] + xb[p]*wb[q];
        }
    }
#pragma unroll
    for (int q = 0; q < 5; q++) {
        int j = jg*5 + q;
        if (j < 38) {
            int jm = (j < 6) ? j : j + 2;
#pragma unroll
            for (int p = 0; p < 4; p++) {
                int l = l0 + pg*4 + p;
                g_xdp[dh][(size_t)(b*LL + l)*40 + jm] = acc[p][q];
            }
        }
    }
}

// sum of 2 partials
__device__ __forceinline__ float xdp_sum(size_t idx) {
    return g_xdp[0][idx] + g_xdp[1][idx];
}

// helper: A_n == A_0*(n+1)?
__device__ __forceinline__ bool a_structured(const float* An) {
    bool ok = true;
#pragma unroll
    for (int n = 1; n < NST; n++)
        ok = ok && (fabsf(An[n] - An[0]*(float)(n+1)) <= 1e-5f*(float)(n+1));
    return ok;
}

__device__ __forceinline__ float softplusf(float a) {
    return (a > 20.f) ? a : __logf(1.f + __expf(a));
}

// ---------------- K4a: scan pass A (256 thr, full-row staging, fused delta) ----------------
__global__ void k4a_scanA(const float* __restrict__ Wd, const float* __restrict__ bde) {
    __shared__ float sXD[CLEN*40];
    int tid = threadIdx.x;
    int d4 = blockIdx.x*256 + tid;
    int c  = blockIdx.y;
    int b  = blockIdx.z;
    int l0 = c*CLEN;
    for (int i = tid; i < CLEN*40; i += 256)
        sXD[i] = xdp_sum((size_t)(b*LL + l0)*40 + i);
    __syncthreads();

    float wd[6];
#pragma unroll
    for (int r = 0; r < 6; r++) wd[r] = Wd[r*768 + d4];
    float bd = bde[d4];

    float An[NST];
#pragma unroll
    for (int n = 0; n < NST; n++) An[n] = g_A[d4*NST + n];
    bool sA = a_structured(An);
    bool fwd = d4 < 384;
    int du = d4 % 192;
    float S = 0.f;

    if (sA) {
        ull h2[8];
#pragma unroll
        for (int k = 0; k < 8; k++) h2[k] = 0ull;
        for (int i = 0; i < CLEN; i++) {
            const float* row = sXD + i*40;
            float a0 = bd;
#pragma unroll
            for (int r = 0; r < 6; r++) a0 = fmaf(row[r], wd[r], a0);
            float dl = softplusf(a0);
            S += dl;
            int l = l0 + i;
            int lu = fwd ? l : (LL-1-l);
            float u = g_xc[(size_t)(b*LL + lu)*192 + du];
            float s = dl*u;
            float e1 = __expf(dl*An[0]);
            ull av[8];
            av_ladder(e1, av);
            ull s2 = pk2(s, s);
            const ull* b2 = (const ull*)(row + 8);
#pragma unroll
            for (int k = 0; k < 8; k++)
                h2[k] = f2fma(av[k], h2[k], f2mul(s2, b2[k]));
        }
        size_t idx0 = ((size_t)(b*NCH + c)*768 + d4)*NST;
        float E = __expf(S*An[0]);
        float a = E;
        float4* H4 = (float4*)(g_chH + idx0);
        float4* P4 = (float4*)(g_chP + idx0);
#pragma unroll
        for (int k = 0; k < 4; k++) {
            float2 ha = upk2(h2[2*k]), hbv = upk2(h2[2*k+1]);
            H4[k] = make_float4(ha.x, ha.y, hbv.x, hbv.y);
            float p0 = a; a *= E;
            float p1 = a; a *= E;
            float p2s = a; a *= E;
            float p3 = a; a *= E;
            P4[k] = make_float4(p0, p1, p2s, p3);
        }
    } else {
        float h[NST];
#pragma unroll
        for (int n = 0; n < NST; n++) h[n] = 0.f;
        for (int i = 0; i < CLEN; i++) {
            const float* row = sXD + i*40;
            float a0 = bd;
#pragma unroll
            for (int r = 0; r < 6; r++) a0 = fmaf(row[r], wd[r], a0);
            float dl = softplusf(a0);
            S += dl;
            int l = l0 + i;
            int lu = fwd ? l : (LL-1-l);
            float u = g_xc[(size_t)(b*LL + lu)*192 + du];
            float s = dl*u;
            const float* bn = row + 8;
#pragma unroll
            for (int n = 0; n < NST; n++) {
                float a = __expf(dl*An[n]);
                h[n] = fmaf(a, h[n], s*bn[n]);
            }
        }
        float p[NST];
#pragma unroll
        for (int n = 0; n < NST; n++) p[n] = __expf(S*An[n]);
        size_t idx0 = ((size_t)(b*NCH + c)*768 + d4)*NST;
        float4* H4 = (float4*)(g_chH + idx0);
        float4* P4 = (float4*)(g_chP + idx0);
#pragma unroll
        for (int k = 0; k < 4; k++) {
            H4[k] = make_float4(h[4*k],h[4*k+1],h[4*k+2],h[4*k+3]);
            P4[k] = make_float4(p[4*k],p[4*k+1],p[4*k+2],p[4*k+3]);
        }
    }
}

// ---------------- K4b: prefix over chunks -> g_h0 ----------------
__global__ void k4b_prefix() {
    int g = blockIdx.x*256 + threadIdx.x;
    int n  = g & 15;
    int d4 = (g >> 4) % 768;
    int b  = g / (16*768);
    size_t base = ((size_t)b*NCH*768 + d4)*NST + n;
    float h = 0.f;
#pragma unroll 4
    for (int c = 0; c < NCH; c++) {
        size_t idx = base + (size_t)c*768*NST;
        float hc = g_chH[idx];
        float pp = g_chP[idx];
        g_h0[idx] = h;
        h = fmaf(pp, h, hc);
    }
}

// ---------------- K4c: scan pass C (256 thr, replay with h0, emit y) ----------------
__global__ void k4c_scanC(const float* __restrict__ Dp,
                          const float* __restrict__ Wd, const float* __restrict__ bde) {
    __shared__ float sXD[CLEN*40];
    int tid = threadIdx.x;
    int d4 = blockIdx.x*256 + tid;
    int c  = blockIdx.y;
    int b  = blockIdx.z;
    int l0 = c*CLEN;
    for (int i = tid; i < CLEN*40; i += 256)
        sXD[i] = xdp_sum((size_t)(b*LL + l0)*40 + i);
    __syncthreads();

    float wd[6];
#pragma unroll
    for (int r = 0; r < 6; r++) wd[r] = Wd[r*768 + d4];
    float bd = bde[d4];

    float An[NST];
#pragma unroll
    for (int n = 0; n < NST; n++) An[n] = g_A[d4*NST + n];
    bool sA = a_structured(An);
    bool fwd = d4 < 384;
    int du = d4 % 192;
    float dp = Dp[d4];

    size_t idx0 = ((size_t)(b*NCH + c)*768 + d4)*NST;
    const float4* H4 = (const float4*)(g_h0 + idx0);

    if (sA) {
        ull h2[8];
#pragma unroll
        for (int k = 0; k < 4; k++) {
            float4 hv = H4[k];
            h2[2*k]   = pk2(hv.x, hv.y);
            h2[2*k+1] = pk2(hv.z, hv.w);
        }
        for (int i = 0; i < CLEN; i++) {
            const float* row = sXD + i*40;
            float a0 = bd;
#pragma unroll
            for (int r = 0; r < 6; r++) a0 = fmaf(row[r], wd[r], a0);
            float dl = softplusf(a0);
            int l = l0 + i;
            int lu = fwd ? l : (LL-1-l);
            float u = g_xc[(size_t)(b*LL + lu)*192 + du];
            float s = dl*u;
            float e1 = __expf(dl*An[0]);
            ull av[8];
            av_ladder(e1, av);
            ull s2 = pk2(s, s);
            const ull* b2 = (const ull*)(row + 8);
            const ull* c2 = (const ull*)(row + 24);
            ull y2 = 0ull;
#pragma unroll
            for (int k = 0; k < 8; k++) {
                h2[k] = f2fma(av[k], h2[k], f2mul(s2, b2[k]));
                y2 = f2fma(h2[k], c2[k], y2);
            }
            float2 yy = upk2(y2);
            g_y[(size_t)(b*LL + l)*768 + d4] = dp*u + yy.x + yy.y;
        }
    } else {
        float h[NST];
#pragma unroll
        for (int k = 0; k < 4; k++) {
            float4 hv = H4[k];
            h[4*k] = hv.x; h[4*k+1] = hv.y; h[4*k+2] = hv.z; h[4*k+3] = hv.w;
        }
        for (int i = 0; i < CLEN; i++) {
            const float* row = sXD + i*40;
            float a0 = bd;
#pragma unroll
            for (int r = 0; r < 6; r++) a0 = fmaf(row[r], wd[r], a0);
            float dl = softplusf(a0);
            int l = l0 + i;
            int lu = fwd ? l : (LL-1-l);
            float u = g_xc[(size_t)(b*LL + lu)*192 + du];
            float s = dl*u;
            const float* bn = row + 8;
            const float* cn = row + 24;
            float y = dp*u;
#pragma unroll
            for (int n = 0; n < NST; n++) {
                float a = __expf(dl*An[n]);
                h[n] = fmaf(a, h[n], s*bn[n]);
                y = fmaf(h[n], cn[n], y);
            }
            g_y[(size_t)(b*LL + l)*768 + d4] = y;
        }
    }
}

// ---------------- K5a: combine + LN + gate, 32-px tile, coalesced g_gT writes ----------------
__global__ void k5a_gate(const float* __restrict__ ln_g, const float* __restrict__ ln_b) {
    __shared__ float sT[32][193];      // 24.7KB
    int tid = threadIdx.x;
    int warp = tid >> 5, lane = tid & 31;
    int b  = blockIdx.y;
    int p0 = blockIdx.x*32;

    float lg[6], lb[6];
#pragma unroll
    for (int k = 0; k < 6; k++) {
        int ch = lane + 32*k;
        lg[k] = ln_g[ch];
        lb[k] = ln_b[ch];
    }

    for (int pi = warp; pi < 32; pi += 8) {
        int p  = p0 + pi;
        int pf = LL - 1 - p;
        const float* yr  = g_y + (size_t)(b*LL + p)*768;
        const float* yrf = g_y + (size_t)(b*LL + pf)*768;

        float v[6];
        float s1 = 0.f, s2 = 0.f;
#pragma unroll
        for (int k = 0; k < 6; k++) {
            int ch = lane + 32*k;
            float vv = yr[ch] + yr[192+ch] + yrf[384+ch] + yrf[576+ch];
            v[k] = vv;
            s1 += vv; s2 += vv*vv;
        }
#pragma unroll
        for (int off = 16; off >= 1; off >>= 1) {
            s1 += __shfl_xor_sync(0xffffffffu, s1, off);
            s2 += __shfl_xor_sync(0xffffffffu, s2, off);
        }
        float mu = s1 * (1.f/192.f);
        float var = s2 * (1.f/192.f) - mu*mu;
        float rstd = rsqrtf(var + 1e-5f);

        const float* zrow = g_xz + (size_t)(b*LL + p)*384 + 192;
#pragma unroll
        for (int k = 0; k < 6; k++) {
            int ch = lane + 32*k;
            float yn = (v[k] - mu)*rstd*lg[k] + lb[k];
            float z  = zrow[ch];
            sT[pi][ch] = yn * __fdividef(z, 1.f + __expf(-z));
        }
    }
    __syncthreads();
    // coalesced: warp writes 32 consecutive pixels of one channel (128B lines)
    for (int i = tid; i < 192*32; i += 256) {
        int ch = i >> 5, pp = i & 31;
        g_gT[(size_t)(b*192 + ch)*LL + p0 + pp] = sT[pp][ch];
    }
}

// ---------------- K5b: out GEMM (192 -> 96), f32x2, reads d-major g_gT ----------------
__global__ void k5b_out(const float* __restrict__ W_out, float* __restrict__ out) {
    __shared__ float sG [32*68];
    __shared__ float sWd[32*192];
    int tid = threadIdx.x;
    int b  = blockIdx.y;
    int l0 = blockIdx.x*64;
    int eg = tid & 31;
    int jq = tid >> 5;
    ull acc[3][4];
#pragma unroll
    for (int e = 0; e < 3; e++)
#pragma unroll
        for (int p = 0; p < 4; p++) acc[e][p] = 0ull;

    for (int k0 = 0; k0 < 192; k0 += 32) {
        __syncthreads();
        for (int i = tid; i < 32*64; i += 256) {
            int dd = i >> 6, pix = i & 63;
            sG[dd*68 + pix] = g_gT[(size_t)(b*192 + k0 + dd)*LL + l0 + pix];
        }
        for (int i = tid; i < 32*96; i += 256) {
            int dd = i/96, cc = i%96;
            float v = W_out[k0*96 + i];
            ((float2*)sWd)[dd*96 + cc] = make_float2(v, v);
        }
        __syncthreads();
#pragma unroll 4
        for (int dd = 0; dd < 32; dd++) {
            ulonglong2 xa = *(const ulonglong2*)(sG + dd*68 + jq*8);
            ulonglong2 xb = *(const ulonglong2*)(sG + dd*68 + jq*8 + 4);
            const ull* wr = (const ull*)sWd + dd*96;
#pragma unroll
            for (int e = 0; e < 3; e++) {
                ull w = wr[e*32 + eg];
                acc[e][0] = f2fma(xa.x, w, acc[e][0]);
                acc[e][1] = f2fma(xa.y, w, acc[e][1]);
                acc[e][2] = f2fma(xb.x, w, acc[e][2]);
                acc[e][3] = f2fma(xb.y, w, acc[e][3]);
            }
        }
    }
#pragma unroll
    for (int e = 0; e < 3; e++) {
        int cc = e*32 + eg;
        float2 v0 = upk2(acc[e][0]), v1 = upk2(acc[e][1]);
        float2 v2 = upk2(acc[e][2]), v3 = upk2(acc[e][3]);
        float* op = out + (size_t)(b*96 + cc)*LL + l0 + jq*8;
        *(float4*)(op)     = make_float4(v0.x, v0.y, v1.x, v1.y);
        *(float4*)(op + 4) = make_float4(v2.x, v2.y, v3.x, v3.y);
    }
}

// ---------------- launch ----------------
extern "C" void kernel_launch(void* const* d_in, const int* in_sizes, int n_in,
                              void* d_out, int out_size) {
    const float* x       = (const float*)d_in[0];
    const float* W_in    = (const float*)d_in[1];
    const float* b_in    = (const float*)d_in[2];
    const float* w_dw    = (const float*)d_in[3];
    const float* b_dw    = (const float*)d_in[4];
    const float* A_log   = (const float*)d_in[5];
    const float* Dp      = (const float*)d_in[6];
    const float* W_x     = (const float*)d_in[7];
    const float* W_delta = (const float*)d_in[8];
    const float* b_delta = (const float*)d_in[9];
    const float* ln_g    = (const float*)d_in[10];
    const float* ln_b    = (const float*)d_in[11];
    const float* W_out   = (const float*)d_in[12];
    float* out = (float*)d_out;

    k1_inproj<<<dim3(LL/32, BB), 256>>>(x, W_in, b_in, A_log, W_x);
    k2_conv<<<(BB*HH*24*192)/256, 256>>>(w_dw, b_dw);
    k3a_xdbl<<<dim3(72, 2, BB), 256>>>();
    k4a_scanA<<<dim3(3, NCH, BB), 256>>>(W_delta, b_delta);
    k4b_prefix<<<(BB*768*16)/256, 256>>>();
    k4c_scanC<<<dim3(3, NCH, BB), 256>>>(Dp, W_delta, b_delta);
    k5a_gate<<<dim3(LL/32, BB), 256>>>(ln_g, ln_b);
    k5b_out<<<dim3(LL/64, BB), 256>>>(W_out, out);
}

// round 13
// speedup vs baseline: 1.0165x; 1.0165x over previous
#include <cuda_runtime.h>
#include <cuda_bf16.h>
#include <math.h>

#define BB   2
#define LL   9216
#define HH   96
#define WIMG 96
#define D2C  192
#define D4C  768
#define NST  16
#define NCH  96
#define CLEN 96

typedef unsigned long long ull;

// ---------------- scratch (device globals; no allocation) ----------------
__device__ float g_xz   [BB*LL*384];       // (b,l,384): xx | z
__device__ float g_xc   [BB*LL*D2C];       // conv+silu output, (b,l,192)
__device__ float g_xdp  [2][BB*LL*40];     // k3a partials (per d-half)
__device__ float g_y    [BB*LL*D4C];       // scan outputs
__device__ float g_gT   [BB*D2C*LL];       // gated values, d-major transposed
__device__ float g_chH  [BB*NCH*D4C*NST];  // chunk local end-state
__device__ float g_chP  [BB*NCH*D4C*NST];  // chunk a-products
__device__ float g_h0   [BB*NCH*D4C*NST];  // per-chunk initial states
__device__ float g_A    [D4C*NST];         // -exp(A_log)
__device__ float g_Wf   [D2C*40];          // folded forward W_x (padded)
__device__ float g_Wb   [D2C*40];          // folded backward W_x (padded)

// ---------------- packed f32x2 helpers ----------------
__device__ __forceinline__ ull pk2(float lo, float hi) {
    ull r;
    asm("mov.b64 %0, {%1, %2};" : "=l"(r) : "f"(lo), "f"(hi));
    return r;
}
__device__ __forceinline__ float2 upk2(ull v) {
    float2 r;
    asm("mov.b64 {%0, %1}, %2;" : "=f"(r.x), "=f"(r.y) : "l"(v));
    return r;
}
__device__ __forceinline__ ull f2mul(ull a, ull b) {
    ull d;
    asm("mul.rn.f32x2 %0, %1, %2;" : "=l"(d) : "l"(a), "l"(b));
    return d;
}
__device__ __forceinline__ ull f2fma(ull a, ull b, ull c) {
    ull d;
    asm("fma.rn.f32x2 %0, %1, %2, %3;" : "=l"(d) : "l"(a), "l"(b), "l"(c));
    return d;
}

// log-depth ladder: av[k] = (e1^(2k+1), e1^(2k+2)), k=0..7
__device__ __forceinline__ void av_ladder(float e1, ull* av) {
    float e2 = e1*e1;
    float e4 = e2*e2;
    float e8 = e4*e4;
    ull p2 = pk2(e2, e2), p4 = pk2(e4, e4), p8 = pk2(e8, e8);
    av[0] = pk2(e1, e2);
    av[1] = f2mul(av[0], p2);
    av[2] = f2mul(av[0], p4);
    av[3] = f2mul(av[1], p4);
    av[4] = f2mul(av[0], p8);
    av[5] = f2mul(av[1], p8);
    av[6] = f2mul(av[2], p8);
    av[7] = f2mul(av[3], p8);
}

// ---------------- K1: in-projection GEMM + folded prep ----------------
__global__ void k1_inproj(const float* __restrict__ x,
                          const float* __restrict__ W_in,
                          const float* __restrict__ b_in,
                          const float* __restrict__ A_log,
                          const float* __restrict__ W_x) {
    __shared__ float sXd[24*64];     // duplicated pixels: (x,x) pairs
    __shared__ float sW [24*384];
    int tid = threadIdx.x;
    int b  = blockIdx.y;
    int l0 = blockIdx.x*32;

    // folded prep (blocks of b==0 only; no consumer until k3a/k4a)
    if (b == 0) {
        int i = blockIdx.x*256 + tid;
        if (i < D4C*NST) g_A[i] = -expf(A_log[i]);
        if (i < D2C*40) {
            int d = i/40, j = i%40;
            float vf = 0.f, vb = 0.f;
            if (j < 38) {
                vf = W_x[d*38+j]       + W_x[(d+192)*38+j];
                vb = W_x[(d+384)*38+j] + W_x[(d+576)*38+j];
            }
            g_Wf[i] = vf;
            g_Wb[i] = vb;
        }
    }

    int eg = tid & 31;
    int jq = tid >> 5;
    ull acc[6][4];
#pragma unroll
    for (int k = 0; k < 6; k++)
#pragma unroll
        for (int p = 0; p < 4; p++) acc[k][p] = 0ull;

    for (int c0 = 0; c0 < 96; c0 += 24) {
        __syncthreads();
        for (int i = tid; i < 24*32; i += 256) {
            int c = i >> 5, j = i & 31;
            float v = x[(b*96 + c0 + c)*LL + l0 + j];
            ((float2*)sXd)[c*32 + j] = make_float2(v, v);
        }
        for (int i = tid; i < 24*384; i += 256)
            sW[i] = W_in[c0*384 + i];
        __syncthreads();
#pragma unroll 4
        for (int cc = 0; cc < 24; cc++) {
            ull xd[4];
#pragma unroll
            for (int p = 0; p < 4; p++)
                xd[p] = ((const ull*)sXd)[cc*32 + jq*4 + p];
            const ull* wrow = (const ull*)(sW + cc*384);
#pragma unroll
            for (int k = 0; k < 6; k++) {
                ull wk = wrow[eg + 32*k];
#pragma unroll
                for (int p = 0; p < 4; p++)
                    acc[k][p] = f2fma(xd[p], wk, acc[k][p]);
            }
        }
    }
    int lbase = l0 + jq*4;
#pragma unroll
    for (int k = 0; k < 6; k++) {
        int e0 = 2*(eg + 32*k);
        float2 bb = *(const float2*)(b_in + e0);
#pragma unroll
        for (int p = 0; p < 4; p++) {
            float2 v = upk2(acc[k][p]);
            v.x += bb.x; v.y += bb.y;
            *(float2*)(g_xz + (size_t)(b*LL + lbase + p)*384 + e0) = v;
        }
    }
}

// ---------------- K2: depthwise 3x3 conv + bias + SiLU (4 px/thread) ----------------
__global__ void k2_conv(const float* __restrict__ w_dw, const float* __restrict__ b_dw) {
    int t = blockIdx.x*256 + threadIdx.x;
    int d = t % 192;
    int rem = t / 192;
    int w4 = rem % 24;
    int rem2 = rem / 24;
    int h = rem2 % HH;
    int b = rem2 / HH;
    int w0 = w4*4;

    float wt[9];
#pragma unroll
    for (int k = 0; k < 9; k++) wt[k] = w_dw[d*9 + k];
    float bias = b_dw[d];
    float acc[4] = {bias, bias, bias, bias};

#pragma unroll
    for (int kh = -1; kh <= 1; kh++) {
        int hh = h + kh;
        if (hh < 0 || hh >= HH) continue;
        float v[6];
#pragma unroll
        for (int c = 0; c < 6; c++) {
            int ww = w0 + c - 1;
            v[c] = (ww >= 0 && ww < WIMG)
                 ? g_xz[(size_t)(b*LL + hh*WIMG + ww)*384 + d] : 0.f;
        }
#pragma unroll
        for (int p = 0; p < 4; p++)
#pragma unroll
            for (int kw = 0; kw < 3; kw++)
                acc[p] = fmaf(v[p+kw], wt[(kh+1)*3 + kw], acc[p]);
    }
#pragma unroll
    for (int p = 0; p < 4; p++) {
        float a = acc[p];
        g_xc[(size_t)(b*LL + h*WIMG + w0 + p)*192 + d] = __fdividef(a, 1.f + __expf(-a));
    }
}

// ---------------- K3a: x_dbl partials, chunked W staging (round-6, DO NOT TOUCH) ----------------
__global__ void k3a_xdbl() {
    __shared__ float sXf[32*132];
    __shared__ float sXb[32*132];
    __shared__ float sWf[32*40];
    __shared__ float sWb[32*40];
    int tid = threadIdx.x;
    int b  = blockIdx.z;
    int dh = blockIdx.y;
    int l0 = blockIdx.x*128;
    int d0 = dh*96;
    int pg = tid >> 3;
    int jg = tid & 7;

    float acc[4][5];
#pragma unroll
    for (int p = 0; p < 4; p++)
#pragma unroll
        for (int q = 0; q < 5; q++) acc[p][q] = 0.f;

    for (int ch = 0; ch < 3; ch++) {
        __syncthreads();
        int db = d0 + ch*32;
        for (int i = tid; i < 128*32; i += 256) {
            int pix = i >> 5, dd = i & 31;
            int l = l0 + pix;
            sXf[dd*132 + pix] = g_xc[(size_t)(b*LL + l)*192 + db + dd];
            sXb[dd*132 + pix] = g_xc[(size_t)(b*LL + (LL-1-l))*192 + db + dd];
        }
        for (int i = tid; i < 32*40; i += 256) {
            sWf[i] = g_Wf[db*40 + i];
            sWb[i] = g_Wb[db*40 + i];
        }
        __syncthreads();
#pragma unroll 4
        for (int dd = 0; dd < 32; dd++) {
            float4 xf4 = *(const float4*)(sXf + dd*132 + pg*4);
            float4 xb4 = *(const float4*)(sXb + dd*132 + pg*4);
            float xf[4] = {xf4.x, xf4.y, xf4.z, xf4.w};
            float xb[4] = {xb4.x, xb4.y, xb4.z, xb4.w};
            int wrow = dd*40 + jg*5;
            float wf[5], wb[5];
#pragma unroll
            for (int q = 0; q < 5; q++) { wf[q] = sWf[wrow+q]; wb[q] = sWb[wrow+q]; }
#pragma unroll
            for (int p = 0; p < 4; p++)
#pragma unroll
                for (int q = 0; q < 5; q++)
                    acc[p][q] += xf[p]*wf[q] + xb[p]*wb[q];
        }
    }
#pragma unroll
    for (int q = 0; q < 5; q++) {
        int j = jg*5 + q;
        if (j < 38) {
            int jm = (j < 6) ? j : j + 2;
#pragma unroll
            for (int p = 0; p < 4; p++) {
                int l = l0 + pg*4 + p;
                g_xdp[dh][(size_t)(b*LL + l)*40 + jm] = acc[p][q];
            }
        }
    }
}

// sum of 2 partials
__device__ __forceinline__ float xdp_sum(size_t idx) {
    return g_xdp[0][idx] + g_xdp[1][idx];
}

// helper: A_n == A_0*(n+1)?
__device__ __forceinline__ bool a_structured(const float* An) {
    bool ok = true;
#pragma unroll
    for (int n = 1; n < NST; n++)
        ok = ok && (fabsf(An[n] - An[0]*(float)(n+1)) <= 1e-5f*(float)(n+1));
    return ok;
}

__device__ __forceinline__ float softplusf(float a) {
    return (a > 20.f) ? a : __logf(1.f + __expf(a));
}

// ---------------- K4a: scan pass A (256 thr, 4 CTAs/SM, fused delta) ----------------
__global__ void __launch_bounds__(256, 4)
k4a_scanA(const float* __restrict__ Wd, const float* __restrict__ bde) {
    __shared__ float sXD[CLEN*40];
    int tid = threadIdx.x;
    int d4 = blockIdx.x*256 + tid;
    int c  = blockIdx.y;
    int b  = blockIdx.z;
    int l0 = c*CLEN;
    for (int i = tid; i < CLEN*40; i += 256)
        sXD[i] = xdp_sum((size_t)(b*LL + l0)*40 + i);
    __syncthreads();

    float wd[6];
#pragma unroll
    for (int r = 0; r < 6; r++) wd[r] = Wd[r*768 + d4];
    float bd = bde[d4];

    float An[NST];
#pragma unroll
    for (int n = 0; n < NST; n++) An[n] = g_A[d4*NST + n];
    bool sA = a_structured(An);
    bool fwd = d4 < 384;
    int du = d4 % 192;
    float S = 0.f;

    if (sA) {
        ull h2[8];
#pragma unroll
        for (int k = 0; k < 8; k++) h2[k] = 0ull;
        for (int i = 0; i < CLEN; i++) {
            const float* row = sXD + i*40;
            float a0 = bd;
#pragma unroll
            for (int r = 0; r < 6; r++) a0 = fmaf(row[r], wd[r], a0);
            float dl = softplusf(a0);
            S += dl;
            int l = l0 + i;
            int lu = fwd ? l : (LL-1-l);
            float u = g_xc[(size_t)(b*LL + lu)*192 + du];
            float s = dl*u;
            float e1 = __expf(dl*An[0]);
            ull av[8];
            av_ladder(e1, av);
            ull s2 = pk2(s, s);
            const ull* b2 = (const ull*)(row + 8);
#pragma unroll
            for (int k = 0; k < 8; k++)
                h2[k] = f2fma(av[k], h2[k], f2mul(s2, b2[k]));
        }
        size_t idx0 = ((size_t)(b*NCH + c)*768 + d4)*NST;
        float E = __expf(S*An[0]);
        float a = E;
        float4* H4 = (float4*)(g_chH + idx0);
        float4* P4 = (float4*)(g_chP + idx0);
#pragma unroll
        for (int k = 0; k < 4; k++) {
            float2 ha = upk2(h2[2*k]), hbv = upk2(h2[2*k+1]);
            H4[k] = make_float4(ha.x, ha.y, hbv.x, hbv.y);
            float p0 = a; a *= E;
            float p1 = a; a *= E;
            float p2s = a; a *= E;
            float p3 = a; a *= E;
            P4[k] = make_float4(p0, p1, p2s, p3);
        }
    } else {
        float h[NST];
#pragma unroll
        for (int n = 0; n < NST; n++) h[n] = 0.f;
        for (int i = 0; i < CLEN; i++) {
            const float* row = sXD + i*40;
            float a0 = bd;
#pragma unroll
            for (int r = 0; r < 6; r++) a0 = fmaf(row[r], wd[r], a0);
            float dl = softplusf(a0);
            S += dl;
            int l = l0 + i;
            int lu = fwd ? l : (LL-1-l);
            float u = g_xc[(size_t)(b*LL + lu)*192 + du];
            float s = dl*u;
            const float* bn = row + 8;
#pragma unroll
            for (int n = 0; n < NST; n++) {
                float a = __expf(dl*An[n]);
                h[n] = fmaf(a, h[n], s*bn[n]);
            }
        }
        float p[NST];
#pragma unroll
        for (int n = 0; n < NST; n++) p[n] = __expf(S*An[n]);
        size_t idx0 = ((size_t)(b*NCH + c)*768 + d4)*NST;
        float4* H4 = (float4*)(g_chH + idx0);
        float4* P4 = (float4*)(g_chP + idx0);
#pragma unroll
        for (int k = 0; k < 4; k++) {
            H4[k] = make_float4(h[4*k],h[4*k+1],h[4*k+2],h[4*k+3]);
            P4[k] = make_float4(p[4*k],p[4*k+1],p[4*k+2],p[4*k+3]);
        }
    }
}

// ---------------- K4b: prefix over chunks -> g_h0 ----------------
__global__ void k4b_prefix() {
    int g = blockIdx.x*256 + threadIdx.x;
    int n  = g & 15;
    int d4 = (g >> 4) % 768;
    int b  = g / (16*768);
    size_t base = ((size_t)b*NCH*768 + d4)*NST + n;
    float h = 0.f;
#pragma unroll 4
    for (int c = 0; c < NCH; c++) {
        size_t idx = base + (size_t)c*768*NST;
        float hc = g_chH[idx];
        float pp = g_chP[idx];
        g_h0[idx] = h;
        h = fmaf(pp, h, hc);
    }
}

// ---------------- K4c: scan pass C (256 thr, 4 CTAs/SM, replay with h0, emit y) ----------------
__global__ void __launch_bounds__(256, 4)
k4c_scanC(const float* __restrict__ Dp,
          const float* __restrict__ Wd, const float* __restrict__ bde) {
    __shared__ float sXD[CLEN*40];
    int tid = threadIdx.x;
    int d4 = blockIdx.x*256 + tid;
    int c  = blockIdx.y;
    int b  = blockIdx.z;
    int l0 = c*CLEN;
    for (int i = tid; i < CLEN*40; i += 256)
        sXD[i] = xdp_sum((size_t)(b*LL + l0)*40 + i);
    __syncthreads();

    float wd[6];
#pragma unroll
    for (int r = 0; r < 6; r++) wd[r] = Wd[r*768 + d4];
    float bd = bde[d4];

    float An[NST];
#pragma unroll
    for (int n = 0; n < NST; n++) An[n] = g_A[d4*NST + n];
    bool sA = a_structured(An);
    bool fwd = d4 < 384;
    int du = d4 % 192;
    float dp = Dp[d4];

    size_t idx0 = ((size_t)(b*NCH + c)*768 + d4)*NST;
    const float4* H4 = (const float4*)(g_h0 + idx0);

    if (sA) {
        ull h2[8];
#pragma unroll
        for (int k = 0; k < 4; k++) {
            float4 hv = H4[k];
            h2[2*k]   = pk2(hv.x, hv.y);
            h2[2*k+1] = pk2(hv.z, hv.w);
        }
        for (int i = 0; i < CLEN; i++) {
            const float* row = sXD + i*40;
            float a0 = bd;
#pragma unroll
            for (int r = 0; r < 6; r++) a0 = fmaf(row[r], wd[r], a0);
            float dl = softplusf(a0);
            int l = l0 + i;
            int lu = fwd ? l : (LL-1-l);
            float u = g_xc[(size_t)(b*LL + lu)*192 + du];
            float s = dl*u;
            float e1 = __expf(dl*An[0]);
            ull av[8];
            av_ladder(e1, av);
            ull s2 = pk2(s, s);
            const ull* b2 = (const ull*)(row + 8);
            const ull* c2 = (const ull*)(row + 24);
            ull y2 = 0ull;
#pragma unroll
            for (int k = 0; k < 8; k++) {
                h2[k] = f2fma(av[k], h2[k], f2mul(s2, b2[k]));
                y2 = f2fma(h2[k], c2[k], y2);
            }
            float2 yy = upk2(y2);
            g_y[(size_t)(b*LL + l)*768 + d4] = dp*u + yy.x + yy.y;
        }
    } else {
        float h[NST];
#pragma unroll
        for (int k = 0; k < 4; k++) {
            float4 hv = H4[k];
            h[4*k] = hv.x; h[4*k+1] = hv.y; h[4*k+2] = hv.z; h[4*k+3] = hv.w;
        }
        for (int i = 0; i < CLEN; i++) {
            const float* row = sXD + i*40;
            float a0 = bd;
#pragma unroll
            for (int r = 0; r < 6; r++) a0 = fmaf(row[r], wd[r], a0);
            float dl = softplusf(a0);
            int l = l0 + i;
            int lu = fwd ? l : (LL-1-l);
            float u = g_xc[(size_t)(b*LL + lu)*192 + du];
            float s = dl*u;
            const float* bn = row + 8;
            const float* cn = row + 24;
            float y = dp*u;
#pragma unroll
            for (int n = 0; n < NST; n++) {
                float a = __expf(dl*An[n]);
                h[n] = fmaf(a, h[n], s*bn[n]);
                y = fmaf(h[n], cn[n], y);
            }
            g_y[(size_t)(b*LL + l)*768 + d4] = y;
        }
    }
}

// ---------------- K5a: combine + LN + gate, 32-px tile, coalesced g_gT writes ----------------
__global__ void k5a_gate(const float* __restrict__ ln_g, const float* __restrict__ ln_b) {
    __shared__ float sT[32][193];      // 24.7KB
    int tid = threadIdx.x;
    int warp = tid >> 5, lane = tid & 31;
    int b  = blockIdx.y;
    int p0 = blockIdx.x*32;

    float lg[6], lb[6];
#pragma unroll
    for (int k = 0; k < 6; k++) {
        int ch = lane + 32*k;
        lg[k] = ln_g[ch];
        lb[k] = ln_b[ch];
    }

    for (int pi = warp; pi < 32; pi += 8) {
        int p  = p0 + pi;
        int pf = LL - 1 - p;
        const float* yr  = g_y + (size_t)(b*LL + p)*768;
        const float* yrf = g_y + (size_t)(b*LL + pf)*768;

        float v[6];
        float s1 = 0.f, s2 = 0.f;
#pragma unroll
        for (int k = 0; k < 6; k++) {
            int ch = lane + 32*k;
            float vv = yr[ch] + yr[192+ch] + yrf[384+ch] + yrf[576+ch];
            v[k] = vv;
            s1 += vv; s2 += vv*vv;
        }
#pragma unroll
        for (int off = 16; off >= 1; off >>= 1) {
            s1 += __shfl_xor_sync(0xffffffffu, s1, off);
            s2 += __shfl_xor_sync(0xffffffffu, s2, off);
        }
        float mu = s1 * (1.f/192.f);
        float var = s2 * (1.f/192.f) - mu*mu;
        float rstd = rsqrtf(var + 1e-5f);

        const float* zrow = g_xz + (size_t)(b*LL + p)*384 + 192;
#pragma unroll
        for (int k = 0; k < 6; k++) {
            int ch = lane + 32*k;
            float yn = (v[k] - mu)*rstd*lg[k] + lb[k];
            float z  = zrow[ch];
            sT[pi][ch] = yn * __fdividef(z, 1.f + __expf(-z));
        }
    }
    __syncthreads();
    // coalesced: warp writes 32 consecutive pixels of one channel (128B lines)
    for (int i = tid; i < 192*32; i += 256) {
        int ch = i >> 5, pp = i & 31;
        g_gT[(size_t)(b*192 + ch)*LL + p0 + pp] = sT[pp][ch];
    }
}

// ---------------- K5b: out GEMM (192 -> 96), f32x2, reads d-major g_gT ----------------
__global__ void k5b_out(const float* __restrict__ W_out, float* __restrict__ out) {
    __shared__ float sG [32*68];
    __shared__ float sWd[32*192];
    int tid = threadIdx.x;
    int b  = blockIdx.y;
    int l0 = blockIdx.x*64;
    int eg = tid & 31;
    int jq = tid >> 5;
    ull acc[3][4];
#pragma unroll
    for (int e = 0; e < 3; e++)
#pragma unroll
        for (int p = 0; p < 4; p++) acc[e][p] = 0ull;

    for (int k0 = 0; k0 < 192; k0 += 32) {
        __syncthreads();
        for (int i = tid; i < 32*64; i += 256) {
            int dd = i >> 6, pix = i & 63;
            sG[dd*68 + pix] = g_gT[(size_t)(b*192 + k0 + dd)*LL + l0 + pix];
        }
        for (int i = tid; i < 32*96; i += 256) {
            int dd = i/96, cc = i%96;
            float v = W_out[k0*96 + i];
            ((float2*)sWd)[dd*96 + cc] = make_float2(v, v);
        }
        __syncthreads();
#pragma unroll 4
        for (int dd = 0; dd < 32; dd++) {
            ulonglong2 xa = *(const ulonglong2*)(sG + dd*68 + jq*8);
            ulonglong2 xb = *(const ulonglong2*)(sG + dd*68 + jq*8 + 4);
            const ull* wr = (const ull*)sWd + dd*96;
#pragma unroll
            for (int e = 0; e < 3; e++) {
                ull w = wr[e*32 + eg];
                acc[e][0] = f2fma(xa.x, w, acc[e][0]);
                acc[e][1] = f2fma(xa.y, w, acc[e][1]);
                acc[e][2] = f2fma(xb.x, w, acc[e][2]);
                acc[e][3] = f2fma(xb.y, w, acc[e][3]);
            }
        }
    }
#pragma unroll
    for (int e = 0; e < 3; e++) {
        int cc = e*32 + eg;
        float2 v0 = upk2(acc[e][0]), v1 = upk2(acc[e][1]);
        float2 v2 = upk2(acc[e][2]), v3 = upk2(acc[e][3]);
        float* op = out + (size_t)(b*96 + cc)*LL + l0 + jq*8;
        *(float4*)(op)     = make_float4(v0.x, v0.y, v1.x, v1.y);
        *(float4*)(op + 4) = make_float4(v2.x, v2.y, v3.x, v3.y);
    }
}

// ---------------- launch ----------------
extern "C" void kernel_launch(void* const* d_in, const int* in_sizes, int n_in,
                              void* d_out, int out_size) {
    const float* x       = (const float*)d_in[0];
    const float* W_in    = (const float*)d_in[1];
    const float* b_in    = (const float*)d_in[2];
    const float* w_dw    = (const float*)d_in[3];
    const float* b_dw    = (const float*)d_in[4];
    const float* A_log   = (const float*)d_in[5];
    const float* Dp      = (const float*)d_in[6];
    const float* W_x     = (const float*)d_in[7];
    const float* W_delta = (const float*)d_in[8];
    const float* b_delta = (const float*)d_in[9];
    const float* ln_g    = (const float*)d_in[10];
    const float* ln_b    = (const float*)d_in[11];
    const float* W_out   = (const float*)d_in[12];
    float* out = (float*)d_out;

    k1_inproj<<<dim3(LL/32, BB), 256>>>(x, W_in, b_in, A_log, W_x);
    k2_conv<<<(BB*HH*24*192)/256, 256>>>(w_dw, b_dw);
    k3a_xdbl<<<dim3(72, 2, BB), 256>>>();
    k4a_scanA<<<dim3(3, NCH, BB), 256>>>(W_delta, b_delta);
    k4b_prefix<<<(BB*768*16)/256, 256>>>();
    k4c_scanC<<<dim3(3, NCH, BB), 256>>>(Dp, W_delta, b_delta);
    k5a_gate<<<dim3(LL/32, BB), 256>>>(ln_g, ln_b);
    k5b_out<<<dim3(LL/64, BB), 256>>>(W_out, out);
}

// round 14
// speedup vs baseline: 1.0207x; 1.0042x over previous
#include <cuda_runtime.h>
#include <cuda_bf16.h>
#include <math.h>

#define BB   2
#define LL   9216
#define HH   96
#define WIMG 96
#define D2C  192
#define D4C  768
#define NST  16
#define NCH  96
#define CLEN 96

typedef unsigned long long ull;

// ---------------- scratch (device globals; no allocation) ----------------
__device__ float g_xz   [BB*LL*384];       // (b,l,384): xx | z
__device__ float g_xc   [BB*LL*D2C];       // conv+silu output, (b,l,192)
__device__ float g_xdp  [2][BB*LL*40];     // k3a partials (per d-half)
__device__ float g_y    [BB*LL*D4C];       // scan outputs
__device__ float g_gT   [BB*D2C*LL];       // gated values, d-major transposed
__device__ float g_chH  [BB*NCH*D4C*NST];  // chunk local end-state
__device__ float g_chP  [BB*NCH*D4C*NST];  // chunk a-products
__device__ float g_h0   [BB*NCH*D4C*NST];  // per-chunk initial states
__device__ float g_A    [D4C*NST];         // -exp(A_log)
__device__ float g_Wf   [D2C*40];          // folded forward W_x (padded)
__device__ float g_Wb   [D2C*40];          // folded backward W_x (padded)

// ---------------- packed f32x2 helpers ----------------
__device__ __forceinline__ ull pk2(float lo, float hi) {
    ull r;
    asm("mov.b64 %0, {%1, %2};" : "=l"(r) : "f"(lo), "f"(hi));
    return r;
}
__device__ __forceinline__ float2 upk2(ull v) {
    float2 r;
    asm("mov.b64 {%0, %1}, %2;" : "=f"(r.x), "=f"(r.y) : "l"(v));
    return r;
}
__device__ __forceinline__ ull f2mul(ull a, ull b) {
    ull d;
    asm("mul.rn.f32x2 %0, %1, %2;" : "=l"(d) : "l"(a), "l"(b));
    return d;
}
__device__ __forceinline__ ull f2fma(ull a, ull b, ull c) {
    ull d;
    asm("fma.rn.f32x2 %0, %1, %2, %3;" : "=l"(d) : "l"(a), "l"(b), "l"(c));
    return d;
}

// log-depth ladder: av[k] = (e1^(2k+1), e1^(2k+2)), k=0..7
__device__ __forceinline__ void av_ladder(float e1, ull* av) {
    float e2 = e1*e1;
    float e4 = e2*e2;
    float e8 = e4*e4;
    ull p2 = pk2(e2, e2), p4 = pk2(e4, e4), p8 = pk2(e8, e8);
    av[0] = pk2(e1, e2);
    av[1] = f2mul(av[0], p2);
    av[2] = f2mul(av[0], p4);
    av[3] = f2mul(av[1], p4);
    av[4] = f2mul(av[0], p8);
    av[5] = f2mul(av[1], p8);
    av[6] = f2mul(av[2], p8);
    av[7] = f2mul(av[3], p8);
}

// ---------------- K1: in-projection GEMM + folded prep ----------------
__global__ void k1_inproj(const float* __restrict__ x,
                          const float* __restrict__ W_in,
                          const float* __restrict__ b_in,
                          const float* __restrict__ A_log,
                          const float* __restrict__ W_x) {
    __shared__ float sXd[24*64];     // duplicated pixels: (x,x) pairs
    __shared__ float sW [24*384];
    int tid = threadIdx.x;
    int b  = blockIdx.y;
    int l0 = blockIdx.x*32;

    // folded prep (blocks of b==0 only; no consumer until k3a/k4a)
    if (b == 0) {
        int i = blockIdx.x*256 + tid;
        if (i < D4C*NST) g_A[i] = -expf(A_log[i]);
        if (i < D2C*40) {
            int d = i/40, j = i%40;
            float vf = 0.f, vb = 0.f;
            if (j < 38) {
                vf = W_x[d*38+j]       + W_x[(d+192)*38+j];
                vb = W_x[(d+384)*38+j] + W_x[(d+576)*38+j];
            }
            g_Wf[i] = vf;
            g_Wb[i] = vb;
        }
    }

    int eg = tid & 31;
    int jq = tid >> 5;
    ull acc[6][4];
#pragma unroll
    for (int k = 0; k < 6; k++)
#pragma unroll
        for (int p = 0; p < 4; p++) acc[k][p] = 0ull;

    for (int c0 = 0; c0 < 96; c0 += 24) {
        __syncthreads();
        for (int i = tid; i < 24*32; i += 256) {
            int c = i >> 5, j = i & 31;
            float v = x[(b*96 + c0 + c)*LL + l0 + j];
            ((float2*)sXd)[c*32 + j] = make_float2(v, v);
        }
        for (int i = tid; i < 24*384; i += 256)
            sW[i] = W_in[c0*384 + i];
        __syncthreads();
#pragma unroll 4
        for (int cc = 0; cc < 24; cc++) {
            ull xd[4];
#pragma unroll
            for (int p = 0; p < 4; p++)
                xd[p] = ((const ull*)sXd)[cc*32 + jq*4 + p];
            const ull* wrow = (const ull*)(sW + cc*384);
#pragma unroll
            for (int k = 0; k < 6; k++) {
                ull wk = wrow[eg + 32*k];
#pragma unroll
                for (int p = 0; p < 4; p++)
                    acc[k][p] = f2fma(xd[p], wk, acc[k][p]);
            }
        }
    }
    int lbase = l0 + jq*4;
#pragma unroll
    for (int k = 0; k < 6; k++) {
        int e0 = 2*(eg + 32*k);
        float2 bb = *(const float2*)(b_in + e0);
#pragma unroll
        for (int p = 0; p < 4; p++) {
            float2 v = upk2(acc[k][p]);
            v.x += bb.x; v.y += bb.y;
            *(float2*)(g_xz + (size_t)(b*LL + lbase + p)*384 + e0) = v;
        }
    }
}

// ---------------- K2: depthwise 3x3 conv + bias + SiLU (4 px/thread) ----------------
__global__ void k2_conv(const float* __restrict__ w_dw, const float* __restrict__ b_dw) {
    int t = blockIdx.x*256 + threadIdx.x;
    int d = t % 192;
    int rem = t / 192;
    int w4 = rem % 24;
    int rem2 = rem / 24;
    int h = rem2 % HH;
    int b = rem2 / HH;
    int w0 = w4*4;

    float wt[9];
#pragma unroll
    for (int k = 0; k < 9; k++) wt[k] = w_dw[d*9 + k];
    float bias = b_dw[d];
    float acc[4] = {bias, bias, bias, bias};

#pragma unroll
    for (int kh = -1; kh <= 1; kh++) {
        int hh = h + kh;
        if (hh < 0 || hh >= HH) continue;
        float v[6];
#pragma unroll
        for (int c = 0; c < 6; c++) {
            int ww = w0 + c - 1;
            v[c] = (ww >= 0 && ww < WIMG)
                 ? g_xz[(size_t)(b*LL + hh*WIMG + ww)*384 + d] : 0.f;
        }
#pragma unroll
        for (int p = 0; p < 4; p++)
#pragma unroll
            for (int kw = 0; kw < 3; kw++)
                acc[p] = fmaf(v[p+kw], wt[(kh+1)*3 + kw], acc[p]);
    }
#pragma unroll
    for (int p = 0; p < 4; p++) {
        float a = acc[p];
        g_xc[(size_t)(b*LL + h*WIMG + w0 + p)*192 + d] = __fdividef(a, 1.f + __expf(-a));
    }
}

// ---------------- K3a: x_dbl partials, chunked W staging (round-6, DO NOT TOUCH) ----------------
__global__ void k3a_xdbl() {
    __shared__ float sXf[32*132];
    __shared__ float sXb[32*132];
    __shared__ float sWf[32*40];
    __shared__ float sWb[32*40];
    int tid = threadIdx.x;
    int b  = blockIdx.z;
    int dh = blockIdx.y;
    int l0 = blockIdx.x*128;
    int d0 = dh*96;
    int pg = tid >> 3;
    int jg = tid & 7;

    float acc[4][5];
#pragma unroll
    for (int p = 0; p < 4; p++)
#pragma unroll
        for (int q = 0; q < 5; q++) acc[p][q] = 0.f;

    for (int ch = 0; ch < 3; ch++) {
        __syncthreads();
        int db = d0 + ch*32;
        for (int i = tid; i < 128*32; i += 256) {
            int pix = i >> 5, dd = i & 31;
            int l = l0 + pix;
            sXf[dd*132 + pix] = g_xc[(size_t)(b*LL + l)*192 + db + dd];
            sXb[dd*132 + pix] = g_xc[(size_t)(b*LL + (LL-1-l))*192 + db + dd];
        }
        for (int i = tid; i < 32*40; i += 256) {
            sWf[i] = g_Wf[db*40 + i];
            sWb[i] = g_Wb[db*40 + i];
        }
        __syncthreads();
#pragma unroll 4
        for (int dd = 0; dd < 32; dd++) {
            float4 xf4 = *(const float4*)(sXf + dd*132 + pg*4);
            float4 xb4 = *(const float4*)(sXb + dd*132 + pg*4);
            float xf[4] = {xf4.x, xf4.y, xf4.z, xf4.w};
            float xb[4] = {xb4.x, xb4.y, xb4.z, xb4.w};
            int wrow = dd*40 + jg*5;
            float wf[5], wb[5];
#pragma unroll
            for (int q = 0; q < 5; q++) { wf[q] = sWf[wrow+q]; wb[q] = sWb[wrow+q]; }
#pragma unroll
            for (int p = 0; p < 4; p++)
#pragma unroll
                for (int q = 0; q < 5; q++)
                    acc[p][q] += xf[p]*wf[q] + xb[p]*wb[q];
        }
    }
#pragma unroll
    for (int q = 0; q < 5; q++) {
        int j = jg*5 + q;
        if (j < 38) {
            int jm = (j < 6) ? j : j + 2;
#pragma unroll
            for (int p = 0; p < 4; p++) {
                int l = l0 + pg*4 + p;
                g_xdp[dh][(size_t)(b*LL + l)*40 + jm] = acc[p][q];
            }
        }
    }
}

// sum of 2 partials
__device__ __forceinline__ float xdp_sum(size_t idx) {
    return g_xdp[0][idx] + g_xdp[1][idx];
}

// helper: A_n == A_0*(n+1)?
__device__ __forceinline__ bool a_structured(const float* An) {
    bool ok = true;
#pragma unroll
    for (int n = 1; n < NST; n++)
        ok = ok && (fabsf(An[n] - An[0]*(float)(n+1)) <= 1e-5f*(float)(n+1));
    return ok;
}

__device__ __forceinline__ float softplusf(float a) {
    return (a > 20.f) ? a : __logf(1.f + __expf(a));
}

// delta pre-activation from a 16B-aligned row
__device__ __forceinline__ float delta_pre(const float* row, const float* wd, float bd) {
    float4 d03 = *(const float4*)row;
    float2 d45 = *(const float2*)(row + 4);
    float a0 = fmaf(d03.x, wd[0], bd);
    a0 = fmaf(d03.y, wd[1], a0);
    a0 = fmaf(d03.z, wd[2], a0);
    a0 = fmaf(d03.w, wd[3], a0);
    a0 = fmaf(d45.x, wd[4], a0);
    a0 = fmaf(d45.y, wd[5], a0);
    return a0;
}

// load 8 packed pairs (16 floats) via 4x LDS.128 (broadcast, conflict-free)
__device__ __forceinline__ void ld8pairs(const float* p, ull* out) {
    ulonglong2 q0 = *(const ulonglong2*)(p);
    ulonglong2 q1 = *(const ulonglong2*)(p + 4);
    ulonglong2 q2 = *(const ulonglong2*)(p + 8);
    ulonglong2 q3 = *(const ulonglong2*)(p + 12);
    out[0] = q0.x; out[1] = q0.y;
    out[2] = q1.x; out[3] = q1.y;
    out[4] = q2.x; out[5] = q2.y;
    out[6] = q3.x; out[7] = q3.y;
}

// ---------------- K4a: scan pass A (256 thr, 4 CTAs/SM, fused delta) ----------------
__global__ void __launch_bounds__(256, 4)
k4a_scanA(const float* __restrict__ Wd, const float* __restrict__ bde) {
    __shared__ __align__(16) float sXD[CLEN*40];
    int tid = threadIdx.x;
    int d4 = blockIdx.x*256 + tid;
    int c  = blockIdx.y;
    int b  = blockIdx.z;
    int l0 = c*CLEN;
    for (int i = tid; i < CLEN*40; i += 256)
        sXD[i] = xdp_sum((size_t)(b*LL + l0)*40 + i);
    __syncthreads();

    float wd[6];
#pragma unroll
    for (int r = 0; r < 6; r++) wd[r] = Wd[r*768 + d4];
    float bd = bde[d4];

    float An[NST];
#pragma unroll
    for (int n = 0; n < NST; n++) An[n] = g_A[d4*NST + n];
    bool sA = a_structured(An);
    bool fwd = d4 < 384;
    int du = d4 % 192;
    float S = 0.f;

    if (sA) {
        ull h2[8];
#pragma unroll
        for (int k = 0; k < 8; k++) h2[k] = 0ull;
        const float* row = sXD;
        const float* up = g_xc + (size_t)(b*LL + (fwd ? l0 : (LL-1-l0)))*192 + du;
        long ustep = fwd ? 192 : -192;
        for (int i = 0; i < CLEN; i++, row += 40, up += ustep) {
            float a0 = delta_pre(row, wd, bd);
            float dl = softplusf(a0);
            S += dl;
            float u = *up;
            float s = dl*u;
            float e1 = __expf(dl*An[0]);
            ull av[8];
            av_ladder(e1, av);
            ull s2 = pk2(s, s);
            ull bb[8];
            ld8pairs(row + 8, bb);
#pragma unroll
            for (int k = 0; k < 8; k++)
                h2[k] = f2fma(av[k], h2[k], f2mul(s2, bb[k]));
        }
        size_t idx0 = ((size_t)(b*NCH + c)*768 + d4)*NST;
        float E = __expf(S*An[0]);
        float a = E;
        float4* H4 = (float4*)(g_chH + idx0);
        float4* P4 = (float4*)(g_chP + idx0);
#pragma unroll
        for (int k = 0; k < 4; k++) {
            float2 ha = upk2(h2[2*k]), hbv = upk2(h2[2*k+1]);
            H4[k] = make_float4(ha.x, ha.y, hbv.x, hbv.y);
            float p0 = a; a *= E;
            float p1 = a; a *= E;
            float p2s = a; a *= E;
            float p3 = a; a *= E;
            P4[k] = make_float4(p0, p1, p2s, p3);
        }
    } else {
        float h[NST];
#pragma unroll
        for (int n = 0; n < NST; n++) h[n] = 0.f;
        for (int i = 0; i < CLEN; i++) {
            const float* row = sXD + i*40;
            float a0 = bd;
#pragma unroll
            for (int r = 0; r < 6; r++) a0 = fmaf(row[r], wd[r], a0);
            float dl = softplusf(a0);
            S += dl;
            int l = l0 + i;
            int lu = fwd ? l : (LL-1-l);
            float u = g_xc[(size_t)(b*LL + lu)*192 + du];
            float s = dl*u;
            const float* bn = row + 8;
#pragma unroll
            for (int n = 0; n < NST; n++) {
                float a = __expf(dl*An[n]);
                h[n] = fmaf(a, h[n], s*bn[n]);
            }
        }
        float p[NST];
#pragma unroll
        for (int n = 0; n < NST; n++) p[n] = __expf(S*An[n]);
        size_t idx0 = ((size_t)(b*NCH + c)*768 + d4)*NST;
        float4* H4 = (float4*)(g_chH + idx0);
        float4* P4 = (float4*)(g_chP + idx0);
#pragma unroll
        for (int k = 0; k < 4; k++) {
            H4[k] = make_float4(h[4*k],h[4*k+1],h[4*k+2],h[4*k+3]);
            P4[k] = make_float4(p[4*k],p[4*k+1],p[4*k+2],p[4*k+3]);
        }
    }
}

// ---------------- K4b: prefix over chunks -> g_h0 ----------------
__global__ void k4b_prefix() {
    int g = blockIdx.x*256 + threadIdx.x;
    int n  = g & 15;
    int d4 = (g >> 4) % 768;
    int b  = g / (16*768);
    size_t base = ((size_t)b*NCH*768 + d4)*NST + n;
    float h = 0.f;
#pragma unroll 4
    for (int c = 0; c < NCH; c++) {
        size_t idx = base + (size_t)c*768*NST;
        float hc = g_chH[idx];
        float pp = g_chP[idx];
        g_h0[idx] = h;
        h = fmaf(pp, h, hc);
    }
}

// ---------------- K4c: scan pass C (256 thr, 4 CTAs/SM, replay with h0, emit y) ----------------
__global__ void __launch_bounds__(256, 4)
k4c_scanC(const float* __restrict__ Dp,
          const float* __restrict__ Wd, const float* __restrict__ bde) {
    __shared__ __align__(16) float sXD[CLEN*40];
    int tid = threadIdx.x;
    int d4 = blockIdx.x*256 + tid;
    int c  = blockIdx.y;
    int b  = blockIdx.z;
    int l0 = c*CLEN;
    for (int i = tid; i < CLEN*40; i += 256)
        sXD[i] = xdp_sum((size_t)(b*LL + l0)*40 + i);
    __syncthreads();

    float wd[6];
#pragma unroll
    for (int r = 0; r < 6; r++) wd[r] = Wd[r*768 + d4];
    float bd = bde[d4];

    float An[NST];
#pragma unroll
    for (int n = 0; n < NST; n++) An[n] = g_A[d4*NST + n];
    bool sA = a_structured(An);
    bool fwd = d4 < 384;
    int du = d4 % 192;
    float dp = Dp[d4];

    size_t idx0 = ((size_t)(b*NCH + c)*768 + d4)*NST;
    const float4* H4 = (const float4*)(g_h0 + idx0);

    if (sA) {
        ull h2[8];
#pragma unroll
        for (int k = 0; k < 4; k++) {
            float4 hv = H4[k];
            h2[2*k]   = pk2(hv.x, hv.y);
            h2[2*k+1] = pk2(hv.z, hv.w);
        }
        const float* row = sXD;
        const float* up = g_xc + (size_t)(b*LL + (fwd ? l0 : (LL-1-l0)))*192 + du;
        long ustep = fwd ? 192 : -192;
        float* yp = g_y + (size_t)(b*LL + l0)*768 + d4;
        for (int i = 0; i < CLEN; i++, row += 40, up += ustep, yp += 768) {
            float a0 = delta_pre(row, wd, bd);
            float dl = softplusf(a0);
            float u = *up;
            float s = dl*u;
            float e1 = __expf(dl*An[0]);
            ull av[8];
            av_ladder(e1, av);
            ull s2 = pk2(s, s);
            ull bb[8], cc2[8];
            ld8pairs(row + 8, bb);
            ld8pairs(row + 24, cc2);
            ull y2 = 0ull;
#pragma unroll
            for (int k = 0; k < 8; k++) {
                h2[k] = f2fma(av[k], h2[k], f2mul(s2, bb[k]));
                y2 = f2fma(h2[k], cc2[k], y2);
            }
            float2 yy = upk2(y2);
            *yp = dp*u + yy.x + yy.y;
        }
    } else {
        float h[NST];
#pragma unroll
        for (int k = 0; k < 4; k++) {
            float4 hv = H4[k];
            h[4*k] = hv.x; h[4*k+1] = hv.y; h[4*k+2] = hv.z; h[4*k+3] = hv.w;
        }
        for (int i = 0; i < CLEN; i++) {
            const float* row = sXD + i*40;
            float a0 = bd;
#pragma unroll
            for (int r = 0; r < 6; r++) a0 = fmaf(row[r], wd[r], a0);
            float dl = softplusf(a0);
            int l = l0 + i;
            int lu = fwd ? l : (LL-1-l);
            float u = g_xc[(size_t)(b*LL + lu)*192 + du];
            float s = dl*u;
            const float* bn = row + 8;
            const float* cn = row + 24;
            float y = dp*u;
#pragma unroll
            for (int n = 0; n < NST; n++) {
                float a = __expf(dl*An[n]);
                h[n] = fmaf(a, h[n], s*bn[n]);
                y = fmaf(h[n], cn[n], y);
            }
            g_y[(size_t)(b*LL + l)*768 + d4] = y;
        }
    }
}

// ---------------- K5a: combine + LN + gate, 32-px tile, coalesced g_gT writes ----------------
__global__ void k5a_gate(const float* __restrict__ ln_g, const float* __restrict__ ln_b) {
    __shared__ float sT[32][193];      // 24.7KB
    int tid = threadIdx.x;
    int warp = tid >> 5, lane = tid & 31;
    int b  = blockIdx.y;
    int p0 = blockIdx.x*32;

    float lg[6], lb[6];
#pragma unroll
    for (int k = 0; k < 6; k++) {
        int ch = lane + 32*k;
        lg[k] = ln_g[ch];
        lb[k] = ln_b[ch];
    }

    for (int pi = warp; pi < 32; pi += 8) {
        int p  = p0 + pi;
        int pf = LL - 1 - p;
        const float* yr  = g_y + (size_t)(b*LL + p)*768;
        const float* yrf = g_y + (size_t)(b*LL + pf)*768;

        float v[6];
        float s1 = 0.f, s2 = 0.f;
#pragma unroll
        for (int k = 0; k < 6; k++) {
            int ch = lane + 32*k;
            float vv = yr[ch] + yr[192+ch] + yrf[384+ch] + yrf[576+ch];
            v[k] = vv;
            s1 += vv; s2 += vv*vv;
        }
#pragma unroll
        for (int off = 16; off >= 1; off >>= 1) {
            s1 += __shfl_xor_sync(0xffffffffu, s1, off);
            s2 += __shfl_xor_sync(0xffffffffu, s2, off);
        }
        float mu = s1 * (1.f/192.f);
        float var = s2 * (1.f/192.f) - mu*mu;
        float rstd = rsqrtf(var + 1e-5f);

        const float* zrow = g_xz + (size_t)(b*LL + p)*384 + 192;
#pragma unroll
        for (int k = 0; k < 6; k++) {
            int ch = lane + 32*k;
            float yn = (v[k] - mu)*rstd*lg[k] + lb[k];
            float z  = zrow[ch];
            sT[pi][ch] = yn * __fdividef(z, 1.f + __expf(-z));
        }
    }
    __syncthreads();
    // coalesced: warp writes 32 consecutive pixels of one channel (128B lines)
    for (int i = tid; i < 192*32; i += 256) {
        int ch = i >> 5, pp = i & 31;
        g_gT[(size_t)(b*192 + ch)*LL + p0 + pp] = sT[pp][ch];
    }
}

// ---------------- K5b: out GEMM (192 -> 96), f32x2, reads d-major g_gT ----------------
__global__ void k5b_out(const float* __restrict__ W_out, float* __restrict__ out) {
    __shared__ float sG [32*68];
    __shared__ float sWd[32*192];
    int tid = threadIdx.x;
    int b  = blockIdx.y;
    int l0 = blockIdx.x*64;
    int eg = tid & 31;
    int jq = tid >> 5;
    ull acc[3][4];
#pragma unroll
    for (int e = 0; e < 3; e++)
#pragma unroll
        for (int p = 0; p < 4; p++) acc[e][p] = 0ull;

    for (int k0 = 0; k0 < 192; k0 += 32) {
        __syncthreads();
        for (int i = tid; i < 32*64; i += 256) {
            int dd = i >> 6, pix = i & 63;
            sG[dd*68 + pix] = g_gT[(size_t)(b*192 + k0 + dd)*LL + l0 + pix];
        }
        for (int i = tid; i < 32*96; i += 256) {
            int dd = i/96, cc = i%96;
            float v = W_out[k0*96 + i];
            ((float2*)sWd)[dd*96 + cc] = make_float2(v, v);
        }
        __syncthreads();
#pragma unroll 4
        for (int dd = 0; dd < 32; dd++) {
            ulonglong2 xa = *(const ulonglong2*)(sG + dd*68 + jq*8);
            ulonglong2 xb = *(const ulonglong2*)(sG + dd*68 + jq*8 + 4);
            const ull* wr = (const ull*)sWd + dd*96;
#pragma unroll
            for (int e = 0; e < 3; e++) {
                ull w = wr[e*32 + eg];
                acc[e][0] = f2fma(xa.x, w, acc[e][0]);
                acc[e][1] = f2fma(xa.y, w, acc[e][1]);
                acc[e][2] = f2fma(xb.x, w, acc[e][2]);
                acc[e][3] = f2fma(xb.y, w, acc[e][3]);
            }
        }
    }
#pragma unroll
    for (int e = 0; e < 3; e++) {
        int cc = e*32 + eg;
        float2 v0 = upk2(acc[e][0]), v1 = upk2(acc[e][1]);
        float2 v2 = upk2(acc[e][2]), v3 = upk2(acc[e][3]);
        float* op = out + (size_t)(b*96 + cc)*LL + l0 + jq*8;
        *(float4*)(op)     = make_float4(v0.x, v0.y, v1.x, v1.y);
        *(float4*)(op + 4) = make_float4(v2.x, v2.y, v3.x, v3.y);
    }
}

// ---------------- launch ----------------
extern "C" void kernel_launch(void* const* d_in, const int* in_sizes, int n_in,
                              void* d_out, int out_size) {
    const float* x       = (const float*)d_in[0];
    const float* W_in    = (const float*)d_in[1];
    const float* b_in    = (const float*)d_in[2];
    const float* w_dw    = (const float*)d_in[3];
    const float* b_dw    = (const float*)d_in[4];
    const float* A_log   = (const float*)d_in[5];
    const float* Dp      = (const float*)d_in[6];
    const float* W_x     = (const float*)d_in[7];
    const float* W_delta = (const float*)d_in[8];
    const float* b_delta = (const float*)d_in[9];
    const float* ln_g    = (const float*)d_in[10];
    const float* ln_b    = (const float*)d_in[11];
    const float* W_out   = (const float*)d_in[12];
    float* out = (float*)d_out;

    k1_inproj<<<dim3(LL/32, BB), 256>>>(x, W_in, b_in, A_log, W_x);
    k2_conv<<<(BB*HH*24*192)/256, 256>>>(w_dw, b_dw);
    k3a_xdbl<<<dim3(72, 2, BB), 256>>>();
    k4a_scanA<<<dim3(3, NCH, BB), 256>>>(W_delta, b_delta);
    k4b_prefix<<<(BB*768*16)/256, 256>>>();
    k4c_scanC<<<dim3(3, NCH, BB), 256>>>(Dp, W_delta, b_delta);
    k5a_gate<<<dim3(LL/32, BB), 256>>>(ln_g, ln_b);
    k5b_out<<<dim3(LL/64, BB), 256>>>(W_out, out);
}

// round 15
// speedup vs baseline: 1.0245x; 1.0037x over previous
#include <cuda_runtime.h>
#include <cuda_bf16.h>
#include <math.h>

#define BB   2
#define LL   9216
#define HH   96
#define WIMG 96
#define D2C  192
#define D4C  768
#define NST  16
#define NCH  96
#define CLEN 96

typedef unsigned long long ull;

// ---------------- scratch (device globals; no allocation) ----------------
__device__ float g_xz   [BB*LL*384];
__device__ float g_xc   [BB*LL*D2C];
__device__ float g_xdp  [2][BB*LL*40];
__device__ float g_y    [BB*LL*D4C];
__device__ float g_gT   [BB*D2C*LL];
__device__ float g_chH  [BB*NCH*D4C*NST];
__device__ float g_chP  [BB*NCH*D4C*NST];
__device__ float g_h0   [BB*NCH*D4C*NST];
__device__ float g_A    [D4C*NST];
__device__ float g_Wf   [D2C*40];
__device__ float g_Wb   [D2C*40];

// ---------------- packed f32x2 helpers ----------------
__device__ __forceinline__ ull pk2(float lo, float hi) {
    ull r;
    asm("mov.b64 %0, {%1, %2};" : "=l"(r) : "f"(lo), "f"(hi));
    return r;
}
__device__ __forceinline__ float2 upk2(ull v) {
    float2 r;
    asm("mov.b64 {%0, %1}, %2;" : "=f"(r.x), "=f"(r.y) : "l"(v));
    return r;
}
__device__ __forceinline__ ull f2mul(ull a, ull b) {
    ull d;
    asm("mul.rn.f32x2 %0, %1, %2;" : "=l"(d) : "l"(a), "l"(b));
    return d;
}
__device__ __forceinline__ ull f2fma(ull a, ull b, ull c) {
    ull d;
    asm("fma.rn.f32x2 %0, %1, %2, %3;" : "=l"(d) : "l"(a), "l"(b), "l"(c));
    return d;
}

// log-depth ladder: av[k] = (e1^(2k+1), e1^(2k+2)), k=0..7
__device__ __forceinline__ void av_ladder(float e1, ull* av) {
    float e2 = e1*e1;
    float e4 = e2*e2;
    float e8 = e4*e4;
    ull p2 = pk2(e2, e2), p4 = pk2(e4, e4), p8 = pk2(e8, e8);
    av[0] = pk2(e1, e2);
    av[1] = f2mul(av[0], p2);
    av[2] = f2mul(av[0], p4);
    av[3] = f2mul(av[1], p4);
    av[4] = f2mul(av[0], p8);
    av[5] = f2mul(av[1], p8);
    av[6] = f2mul(av[2], p8);
    av[7] = f2mul(av[3], p8);
}

// ---------------- K1: in-projection GEMM + folded prep ----------------
__global__ void k1_inproj(const float* __restrict__ x,
                          const float* __restrict__ W_in,
                          const float* __restrict__ b_in,
                          const float* __restrict__ A_log,
                          const float* __restrict__ W_x) {
    __shared__ float sXd[24*64];
    __shared__ float sW [24*384];
    int tid = threadIdx.x;
    int b  = blockIdx.y;
    int l0 = blockIdx.x*32;

    if (b == 0) {
        int i = blockIdx.x*256 + tid;
        if (i < D4C*NST) g_A[i] = -expf(A_log[i]);
        if (i < D2C*40) {
            int d = i/40, j = i%40;
            float vf = 0.f, vb = 0.f;
            if (j < 38) {
                vf = W_x[d*38+j]       + W_x[(d+192)*38+j];
                vb = W_x[(d+384)*38+j] + W_x[(d+576)*38+j];
            }
            g_Wf[i] = vf;
            g_Wb[i] = vb;
        }
    }

    int eg = tid & 31;
    int jq = tid >> 5;
    ull acc[6][4];
#pragma unroll
    for (int k = 0; k < 6; k++)
#pragma unroll
        for (int p = 0; p < 4; p++) acc[k][p] = 0ull;

    for (int c0 = 0; c0 < 96; c0 += 24) {
        __syncthreads();
        for (int i = tid; i < 24*32; i += 256) {
            int c = i >> 5, j = i & 31;
            float v = x[(b*96 + c0 + c)*LL + l0 + j];
            ((float2*)sXd)[c*32 + j] = make_float2(v, v);
        }
        for (int i = tid; i < 24*384; i += 256)
            sW[i] = W_in[c0*384 + i];
        __syncthreads();
#pragma unroll 4
        for (int cc = 0; cc < 24; cc++) {
            ull xd[4];
#pragma unroll
            for (int p = 0; p < 4; p++)
                xd[p] = ((const ull*)sXd)[cc*32 + jq*4 + p];
            const ull* wrow = (const ull*)(sW + cc*384);
#pragma unroll
            for (int k = 0; k < 6; k++) {
                ull wk = wrow[eg + 32*k];
#pragma unroll
                for (int p = 0; p < 4; p++)
                    acc[k][p] = f2fma(xd[p], wk, acc[k][p]);
            }
        }
    }
    int lbase = l0 + jq*4;
#pragma unroll
    for (int k = 0; k < 6; k++) {
        int e0 = 2*(eg + 32*k);
        float2 bb = *(const float2*)(b_in + e0);
#pragma unroll
        for (int p = 0; p < 4; p++) {
            float2 v = upk2(acc[k][p]);
            v.x += bb.x; v.y += bb.y;
            *(float2*)(g_xz + (size_t)(b*LL + lbase + p)*384 + e0) = v;
        }
    }
}

// ---------------- K2: depthwise 3x3 conv + bias + SiLU (4 px/thread) ----------------
__global__ void k2_conv(const float* __restrict__ w_dw, const float* __restrict__ b_dw) {
    int t = blockIdx.x*256 + threadIdx.x;
    int d = t % 192;
    int rem = t / 192;
    int w4 = rem % 24;
    int rem2 = rem / 24;
    int h = rem2 % HH;
    int b = rem2 / HH;
    int w0 = w4*4;

    float wt[9];
#pragma unroll
    for (int k = 0; k < 9; k++) wt[k] = w_dw[d*9 + k];
    float bias = b_dw[d];
    float acc[4] = {bias, bias, bias, bias};

#pragma unroll
    for (int kh = -1; kh <= 1; kh++) {
        int hh = h + kh;
        if (hh < 0 || hh >= HH) continue;
        float v[6];
#pragma unroll
        for (int c = 0; c < 6; c++) {
            int ww = w0 + c - 1;
            v[c] = (ww >= 0 && ww < WIMG)
                 ? g_xz[(size_t)(b*LL + hh*WIMG + ww)*384 + d] : 0.f;
        }
#pragma unroll
        for (int p = 0; p < 4; p++)
#pragma unroll
            for (int kw = 0; kw < 3; kw++)
                acc[p] = fmaf(v[p+kw], wt[(kh+1)*3 + kw], acc[p]);
    }
#pragma unroll
    for (int p = 0; p < 4; p++) {
        float a = acc[p];
        g_xc[(size_t)(b*LL + h*WIMG + w0 + p)*192 + d] = __fdividef(a, 1.f + __expf(-a));
    }
}

// ---------------- K3a: x_dbl partials (round-6, DO NOT TOUCH) ----------------
__global__ void k3a_xdbl() {
    __shared__ float sXf[32*132];
    __shared__ float sXb[32*132];
    __shared__ float sWf[32*40];
    __shared__ float sWb[32*40];
    int tid = threadIdx.x;
    int b  = blockIdx.z;
    int dh = blockIdx.y;
    int l0 = blockIdx.x*128;
    int d0 = dh*96;
    int pg = tid >> 3;
    int jg = tid & 7;

    float acc[4][5];
#pragma unroll
    for (int p = 0; p < 4; p++)
#pragma unroll
        for (int q = 0; q < 5; q++) acc[p][q] = 0.f;

    for (int ch = 0; ch < 3; ch++) {
        __syncthreads();
        int db = d0 + ch*32;
        for (int i = tid; i < 128*32; i += 256) {
            int pix = i >> 5, dd = i & 31;
            int l = l0 + pix;
            sXf[dd*132 + pix] = g_xc[(size_t)(b*LL + l)*192 + db + dd];
            sXb[dd*132 + pix] = g_xc[(size_t)(b*LL + (LL-1-l))*192 + db + dd];
        }
        for (int i = tid; i < 32*40; i += 256) {
            sWf[i] = g_Wf[db*40 + i];
            sWb[i] = g_Wb[db*40 + i];
        }
        __syncthreads();
#pragma unroll 4
        for (int dd = 0; dd < 32; dd++) {
            float4 xf4 = *(const float4*)(sXf + dd*132 + pg*4);
            float4 xb4 = *(const float4*)(sXb + dd*132 + pg*4);
            float xf[4] = {xf4.x, xf4.y, xf4.z, xf4.w};
            float xb[4] = {xb4.x, xb4.y, xb4.z, xb4.w};
            int wrow = dd*40 + jg*5;
            float wf[5], wb[5];
#pragma unroll
            for (int q = 0; q < 5; q++) { wf[q] = sWf[wrow+q]; wb[q] = sWb[wrow+q]; }
#pragma unroll
            for (int p = 0; p < 4; p++)
#pragma unroll
                for (int q = 0; q < 5; q++)
                    acc[p][q] += xf[p]*wf[q] + xb[p]*wb[q];
        }
    }
#pragma unroll
    for (int q = 0; q < 5; q++) {
        int j = jg*5 + q;
        if (j < 38) {
            int jm = (j < 6) ? j : j + 2;
#pragma unroll
            for (int p = 0; p < 4; p++) {
                int l = l0 + pg*4 + p;
                g_xdp[dh][(size_t)(b*LL + l)*40 + jm] = acc[p][q];
            }
        }
    }
}

__device__ __forceinline__ float xdp_sum(size_t idx) {
    return g_xdp[0][idx] + g_xdp[1][idx];
}

__device__ __forceinline__ bool a_structured(const float* An) {
    bool ok = true;
#pragma unroll
    for (int n = 1; n < NST; n++)
        ok = ok && (fabsf(An[n] - An[0]*(float)(n+1)) <= 1e-5f*(float)(n+1));
    return ok;
}

__device__ __forceinline__ float softplusf(float a) {
    return (a > 20.f) ? a : __logf(1.f + __expf(a));
}

// delta pre-activation via packed dot: 3 f2fma + horizontal add
__device__ __forceinline__ float delta_pre2(const float* row, const ull* wd2, float bd) {
    const ull* r2 = (const ull*)row;
    ull acc = f2mul(r2[0], wd2[0]);
    acc = f2fma(r2[1], wd2[1], acc);
    acc = f2fma(r2[2], wd2[2], acc);
    float2 a = upk2(acc);
    return a.x + a.y + bd;
}

// load 8 packed pairs (16 floats) via 4x LDS.128
__device__ __forceinline__ void ld8pairs(const float* p, ull* out) {
    ulonglong2 q0 = *(const ulonglong2*)(p);
    ulonglong2 q1 = *(const ulonglong2*)(p + 4);
    ulonglong2 q2 = *(const ulonglong2*)(p + 8);
    ulonglong2 q3 = *(const ulonglong2*)(p + 12);
    out[0] = q0.x; out[1] = q0.y;
    out[2] = q1.x; out[3] = q1.y;
    out[4] = q2.x; out[5] = q2.y;
    out[6] = q3.x; out[7] = q3.y;
}

// ---------------- K4a: scan pass A (pipelined u prefetch) ----------------
__global__ void __launch_bounds__(256, 4)
k4a_scanA(const float* __restrict__ Wd, const float* __restrict__ bde) {
    __shared__ __align__(16) float sXD[CLEN*40];
    int tid = threadIdx.x;
    int d4 = blockIdx.x*256 + tid;
    int c  = blockIdx.y;
    int b  = blockIdx.z;
    int l0 = c*CLEN;
    for (int i = tid; i < CLEN*40; i += 256)
        sXD[i] = xdp_sum((size_t)(b*LL + l0)*40 + i);
    __syncthreads();

    float wd[6];
#pragma unroll
    for (int r = 0; r < 6; r++) wd[r] = Wd[r*768 + d4];
    ull wd2[3] = {pk2(wd[0], wd[1]), pk2(wd[2], wd[3]), pk2(wd[4], wd[5])};
    float bd = bde[d4];

    float An[NST];
#pragma unroll
    for (int n = 0; n < NST; n++) An[n] = g_A[d4*NST + n];
    bool sA = a_structured(An);
    bool fwd = d4 < 384;
    int du = d4 % 192;
    float S = 0.f;

    if (sA) {
        ull h2[8];
#pragma unroll
        for (int k = 0; k < 8; k++) h2[k] = 0ull;
        const float* row = sXD;
        const float* up = g_xc + (size_t)(b*LL + (fwd ? l0 : (LL-1-l0)))*192 + du;
        long ustep = fwd ? 192 : -192;
        float u_cur = *up;
        for (int i = 0; i < CLEN; i++, row += 40) {
            up += ustep;
            float u_nxt = (i+1 < CLEN) ? *up : 0.f;   // prefetch next u
            float a0 = delta_pre2(row, wd2, bd);
            float dl = softplusf(a0);
            S += dl;
            float s = dl*u_cur;
            float e1 = __expf(dl*An[0]);
            ull av[8];
            av_ladder(e1, av);
            ull s2 = pk2(s, s);
            ull bb[8];
            ld8pairs(row + 8, bb);
#pragma unroll
            for (int k = 0; k < 8; k++)
                h2[k] = f2fma(av[k], h2[k], f2mul(s2, bb[k]));
            u_cur = u_nxt;
        }
        size_t idx0 = ((size_t)(b*NCH + c)*768 + d4)*NST;
        float E = __expf(S*An[0]);
        float a = E;
        float4* H4 = (float4*)(g_chH + idx0);
        float4* P4 = (float4*)(g_chP + idx0);
#pragma unroll
        for (int k = 0; k < 4; k++) {
            float2 ha = upk2(h2[2*k]), hbv = upk2(h2[2*k+1]);
            H4[k] = make_float4(ha.x, ha.y, hbv.x, hbv.y);
            float p0 = a; a *= E;
            float p1 = a; a *= E;
            float p2s = a; a *= E;
            float p3 = a; a *= E;
            P4[k] = make_float4(p0, p1, p2s, p3);
        }
    } else {
        float h[NST];
#pragma unroll
        for (int n = 0; n < NST; n++) h[n] = 0.f;
        for (int i = 0; i < CLEN; i++) {
            const float* row = sXD + i*40;
            float a0 = bd;
#pragma unroll
            for (int r = 0; r < 6; r++) a0 = fmaf(row[r], wd[r], a0);
            float dl = softplusf(a0);
            S += dl;
            int l = l0 + i;
            int lu = fwd ? l : (LL-1-l);
            float u = g_xc[(size_t)(b*LL + lu)*192 + du];
            float s = dl*u;
            const float* bn = row + 8;
#pragma unroll
            for (int n = 0; n < NST; n++) {
                float a = __expf(dl*An[n]);
                h[n] = fmaf(a, h[n], s*bn[n]);
            }
        }
        float p[NST];
#pragma unroll
        for (int n = 0; n < NST; n++) p[n] = __expf(S*An[n]);
        size_t idx0 = ((size_t)(b*NCH + c)*768 + d4)*NST;
        float4* H4 = (float4*)(g_chH + idx0);
        float4* P4 = (float4*)(g_chP + idx0);
#pragma unroll
        for (int k = 0; k < 4; k++) {
            H4[k] = make_float4(h[4*k],h[4*k+1],h[4*k+2],h[4*k+3]);
            P4[k] = make_float4(p[4*k],p[4*k+1],p[4*k+2],p[4*k+3]);
        }
    }
}

// ---------------- K4b: prefix over chunks -> g_h0 ----------------
__global__ void k4b_prefix() {
    int g = blockIdx.x*256 + threadIdx.x;
    int n  = g & 15;
    int d4 = (g >> 4) % 768;
    int b  = g / (16*768);
    size_t base = ((size_t)b*NCH*768 + d4)*NST + n;
    float h = 0.f;
#pragma unroll 4
    for (int c = 0; c < NCH; c++) {
        size_t idx = base + (size_t)c*768*NST;
        float hc = g_chH[idx];
        float pp = g_chP[idx];
        g_h0[idx] = h;
        h = fmaf(pp, h, hc);
    }
}

// ---------------- K4c: scan pass C (pipelined u prefetch, emit y) ----------------
__global__ void __launch_bounds__(256, 4)
k4c_scanC(const float* __restrict__ Dp,
          const float* __restrict__ Wd, const float* __restrict__ bde) {
    __shared__ __align__(16) float sXD[CLEN*40];
    int tid = threadIdx.x;
    int d4 = blockIdx.x*256 + tid;
    int c  = blockIdx.y;
    int b  = blockIdx.z;
    int l0 = c*CLEN;
    for (int i = tid; i < CLEN*40; i += 256)
        sXD[i] = xdp_sum((size_t)(b*LL + l0)*40 + i);
    __syncthreads();

    float wd[6];
#pragma unroll
    for (int r = 0; r < 6; r++) wd[r] = Wd[r*768 + d4];
    ull wd2[3] = {pk2(wd[0], wd[1]), pk2(wd[2], wd[3]), pk2(wd[4], wd[5])};
    float bd = bde[d4];

    float An[NST];
#pragma unroll
    for (int n = 0; n < NST; n++) An[n] = g_A[d4*NST + n];
    bool sA = a_structured(An);
    bool fwd = d4 < 384;
    int du = d4 % 192;
    float dp = Dp[d4];

    size_t idx0 = ((size_t)(b*NCH + c)*768 + d4)*NST;
    const float4* H4 = (const float4*)(g_h0 + idx0);

    if (sA) {
        ull h2[8];
#pragma unroll
        for (int k = 0; k < 4; k++) {
            float4 hv = H4[k];
            h2[2*k]   = pk2(hv.x, hv.y);
            h2[2*k+1] = pk2(hv.z, hv.w);
        }
        const float* row = sXD;
        const float* up = g_xc + (size_t)(b*LL + (fwd ? l0 : (LL-1-l0)))*192 + du;
        long ustep = fwd ? 192 : -192;
        float* yp = g_y + (size_t)(b*LL + l0)*768 + d4;
        float u_cur = *up;
        for (int i = 0; i < CLEN; i++, row += 40, yp += 768) {
            up += ustep;
            float u_nxt = (i+1 < CLEN) ? *up : 0.f;
            float a0 = delta_pre2(row, wd2, bd);
            float dl = softplusf(a0);
            float s = dl*u_cur;
            float e1 = __expf(dl*An[0]);
            ull av[8];
            av_ladder(e1, av);
            ull s2 = pk2(s, s);
            ull bb[8], cc2[8];
            ld8pairs(row + 8, bb);
            ld8pairs(row + 24, cc2);
            ull y2 = 0ull;
#pragma unroll
            for (int k = 0; k < 8; k++) {
                h2[k] = f2fma(av[k], h2[k], f2mul(s2, bb[k]));
                y2 = f2fma(h2[k], cc2[k], y2);
            }
            float2 yy = upk2(y2);
            *yp = dp*u_cur + yy.x + yy.y;
            u_cur = u_nxt;
        }
    } else {
        float h[NST];
#pragma unroll
        for (int k = 0; k < 4; k++) {
            float4 hv = H4[k];
            h[4*k] = hv.x; h[4*k+1] = hv.y; h[4*k+2] = hv.z; h[4*k+3] = hv.w;
        }
        for (int i = 0; i < CLEN; i++) {
            const float* row = sXD + i*40;
            float a0 = bd;
#pragma unroll
            for (int r = 0; r < 6; r++) a0 = fmaf(row[r], wd[r], a0);
            float dl = softplusf(a0);
            int l = l0 + i;
            int lu = fwd ? l : (LL-1-l);
            float u = g_xc[(size_t)(b*LL + lu)*192 + du];
            float s = dl*u;
            const float* bn = row + 8;
            const float* cn = row + 24;
            float y = dp*u;
#pragma unroll
            for (int n = 0; n < NST; n++) {
                float a = __expf(dl*An[n]);
                h[n] = fmaf(a, h[n], s*bn[n]);
                y = fmaf(h[n], cn[n], y);
            }
            g_y[(size_t)(b*LL + l)*768 + d4] = y;
        }
    }
}

// ---------------- K5a: combine + LN + gate, 32-px tile, coalesced writes ----------------
__global__ void k5a_gate(const float* __restrict__ ln_g, const float* __restrict__ ln_b) {
    __shared__ float sT[32][193];
    int tid = threadIdx.x;
    int warp = tid >> 5, lane = tid & 31;
    int b  = blockIdx.y;
    int p0 = blockIdx.x*32;

    float lg[6], lb[6];
#pragma unroll
    for (int k = 0; k < 6; k++) {
        int ch = lane + 32*k;
        lg[k] = ln_g[ch];
        lb[k] = ln_b[ch];
    }

    for (int pi = warp; pi < 32; pi += 8) {
        int p  = p0 + pi;
        int pf = LL - 1 - p;
        const float* yr  = g_y + (size_t)(b*LL + p)*768;
        const float* yrf = g_y + (size_t)(b*LL + pf)*768;

        float v[6];
        float s1 = 0.f, s2 = 0.f;
#pragma unroll
        for (int k = 0; k < 6; k++) {
            int ch = lane + 32*k;
            float vv = yr[ch] + yr[192+ch] + yrf[384+ch] + yrf[576+ch];
            v[k] = vv;
            s1 += vv; s2 += vv*vv;
        }
#pragma unroll
        for (int off = 16; off >= 1; off >>= 1) {
            s1 += __shfl_xor_sync(0xffffffffu, s1, off);
            s2 += __shfl_xor_sync(0xffffffffu, s2, off);
        }
        float mu = s1 * (1.f/192.f);
        float var = s2 * (1.f/192.f) - mu*mu;
        float rstd = rsqrtf(var + 1e-5f);

        const float* zrow = g_xz + (size_t)(b*LL + p)*384 + 192;
#pragma unroll
        for (int k = 0; k < 6; k++) {
            int ch = lane + 32*k;
            float yn = (v[k] - mu)*rstd*lg[k] + lb[k];
            float z  = zrow[ch];
            sT[pi][ch] = yn * __fdividef(z, 1.f + __expf(-z));
        }
    }
    __syncthreads();
    for (int i = tid; i < 192*32; i += 256) {
        int ch = i >> 5, pp = i & 31;
        g_gT[(size_t)(b*192 + ch)*LL + p0 + pp] = sT[pp][ch];
    }
}

// ---------------- K5b: out GEMM (192 -> 96), f32x2 ----------------
__global__ void __launch_bounds__(256, 4)
k5b_out(const float* __restrict__ W_out, float* __restrict__ out) {
    __shared__ float sG [32*68];
    __shared__ float sWd[32*192];
    int tid = threadIdx.x;
    int b  = blockIdx.y;
    int l0 = blockIdx.x*64;
    int eg = tid & 31;
    int jq = tid >> 5;
    ull acc[3][4];
#pragma unroll
    for (int e = 0; e < 3; e++)
#pragma unroll
        for (int p = 0; p < 4; p++) acc[e][p] = 0ull;

    for (int k0 = 0; k0 < 192; k0 += 32) {
        __syncthreads();
        for (int i = tid; i < 32*64; i += 256) {
            int dd = i >> 6, pix = i & 63;
            sG[dd*68 + pix] = g_gT[(size_t)(b*192 + k0 + dd)*LL + l0 + pix];
        }
        for (int i = tid; i < 32*96; i += 256) {
            int dd = i/96, cc = i%96;
            float v = W_out[k0*96 + i];
            ((float2*)sWd)[dd*96 + cc] = make_float2(v, v);
        }
        __syncthreads();
#pragma unroll 4
        for (int dd = 0; dd < 32; dd++) {
            ulonglong2 xa = *(const ulonglong2*)(sG + dd*68 + jq*8);
            ulonglong2 xb = *(const ulonglong2*)(sG + dd*68 + jq*8 + 4);
            const ull* wr = (const ull*)sWd + dd*96;
#pragma unroll
            for (int e = 0; e < 3; e++) {
                ull w = wr[e*32 + eg];
                acc[e][0] = f2fma(xa.x, w, acc[e][0]);
                acc[e][1] = f2fma(xa.y, w, acc[e][1]);
                acc[e][2] = f2fma(xb.x, w, acc[e][2]);
                acc[e][3] = f2fma(xb.y, w, acc[e][3]);
            }
        }
    }
#pragma unroll
    for (int e = 0; e < 3; e++) {
        int cc = e*32 + eg;
        float2 v0 = upk2(acc[e][0]), v1 = upk2(acc[e][1]);
        float2 v2 = upk2(acc[e][2]), v3 = upk2(acc[e][3]);
        float* op = out + (size_t)(b*96 + cc)*LL + l0 + jq*8;
        *(float4*)(op)     = make_float4(v0.x, v0.y, v1.x, v1.y);
        *(float4*)(op + 4) = make_float4(v2.x, v2.y, v3.x, v3.y);
    }
}

// ---------------- launch ----------------
extern "C" void kernel_launch(void* const* d_in, const int* in_sizes, int n_in,
                              void* d_out, int out_size) {
    const float* x       = (const float*)d_in[0];
    const float* W_in    = (const float*)d_in[1];
    const float* b_in    = (const float*)d_in[2];
    const float* w_dw    = (const float*)d_in[3];
    const float* b_dw    = (const float*)d_in[4];
    const float* A_log   = (const float*)d_in[5];
    const float* Dp      = (const float*)d_in[6];
    const float* W_x     = (const float*)d_in[7];
    const float* W_delta = (const float*)d_in[8];
    const float* b_delta = (const float*)d_in[9];
    const float* ln_g    = (const float*)d_in[10];
    const float* ln_b    = (const float*)d_in[11];
    const float* W_out   = (const float*)d_in[12];
    float* out = (float*)d_out;

    k1_inproj<<<dim3(LL/32, BB), 256>>>(x, W_in, b_in, A_log, W_x);
    k2_conv<<<(BB*HH*24*192)/256, 256>>>(w_dw, b_dw);
    k3a_xdbl<<<dim3(72, 2, BB), 256>>>();
    k4a_scanA<<<dim3(3, NCH, BB), 256>>>(W_delta, b_delta);
    k4b_prefix<<<(BB*768*16)/256, 256>>>();
    k4c_scanC<<<dim3(3, NCH, BB), 256>>>(Dp, W_delta, b_delta);
    k5a_gate<<<dim3(LL/32, BB), 256>>>(ln_g, ln_b);
    k5b_out<<<dim3(LL/64, BB), 256>>>(W_out, out);
}

// round 16
// speedup vs baseline: 1.0517x; 1.0266x over previous
#include <cuda_runtime.h>
#include <cuda_bf16.h>
#include <math.h>

#define BB   2
#define LL   9216
#define HH   96
#define WIMG 96
#define D2C  192
#define D4C  768
#define NST  16
#define NCH  96
#define CLEN 96

typedef unsigned long long ull;

// ---------------- scratch (device globals; no allocation) ----------------
__device__ float g_xz   [BB*LL*384];
__device__ float g_xc   [BB*LL*D2C];
__device__ float g_xdp  [2][BB*LL*40];
__device__ float g_y    [BB*LL*D4C];
__device__ float g_gT   [BB*D2C*LL];
__device__ float g_chH  [BB*NCH*D4C*NST];
__device__ float g_chP  [BB*NCH*D4C*NST];
__device__ float g_h0   [BB*NCH*D4C*NST];
__device__ float g_A    [D4C*NST];
__device__ float g_Wf   [D2C*40];
__device__ float g_Wb   [D2C*40];

// ---------------- packed f32x2 helpers ----------------
__device__ __forceinline__ ull pk2(float lo, float hi) {
    ull r;
    asm("mov.b64 %0, {%1, %2};" : "=l"(r) : "f"(lo), "f"(hi));
    return r;
}
__device__ __forceinline__ float2 upk2(ull v) {
    float2 r;
    asm("mov.b64 {%0, %1}, %2;" : "=f"(r.x), "=f"(r.y) : "l"(v));
    return r;
}
__device__ __forceinline__ ull f2mul(ull a, ull b) {
    ull d;
    asm("mul.rn.f32x2 %0, %1, %2;" : "=l"(d) : "l"(a), "l"(b));
    return d;
}
__device__ __forceinline__ ull f2fma(ull a, ull b, ull c) {
    ull d;
    asm("fma.rn.f32x2 %0, %1, %2, %3;" : "=l"(d) : "l"(a), "l"(b), "l"(c));
    return d;
}

// log-depth ladder: av[k] = (e1^(2k+1), e1^(2k+2)), k=0..7
__device__ __forceinline__ void av_ladder(float e1, ull* av) {
    float e2 = e1*e1;
    float e4 = e2*e2;
    float e8 = e4*e4;
    ull p2 = pk2(e2, e2), p4 = pk2(e4, e4), p8 = pk2(e8, e8);
    av[0] = pk2(e1, e2);
    av[1] = f2mul(av[0], p2);
    av[2] = f2mul(av[0], p4);
    av[3] = f2mul(av[1], p4);
    av[4] = f2mul(av[0], p8);
    av[5] = f2mul(av[1], p8);
    av[6] = f2mul(av[2], p8);
    av[7] = f2mul(av[3], p8);
}

// ---------------- K1: in-projection GEMM + folded prep ----------------
__global__ void k1_inproj(const float* __restrict__ x,
                          const float* __restrict__ W_in,
                          const float* __restrict__ b_in,
                          const float* __restrict__ A_log,
                          const float* __restrict__ W_x) {
    __shared__ float sXd[24*64];
    __shared__ float sW [24*384];
    int tid = threadIdx.x;
    int b  = blockIdx.y;
    int l0 = blockIdx.x*32;

    if (b == 0) {
        int i = blockIdx.x*256 + tid;
        if (i < D4C*NST) g_A[i] = -expf(A_log[i]);
        if (i < D2C*40) {
            int d = i/40, j = i%40;
            float vf = 0.f, vb = 0.f;
            if (j < 38) {
                vf = W_x[d*38+j]       + W_x[(d+192)*38+j];
                vb = W_x[(d+384)*38+j] + W_x[(d+576)*38+j];
            }
            g_Wf[i] = vf;
            g_Wb[i] = vb;
        }
    }

    int eg = tid & 31;
    int jq = tid >> 5;
    ull acc[6][4];
#pragma unroll
    for (int k = 0; k < 6; k++)
#pragma unroll
        for (int p = 0; p < 4; p++) acc[k][p] = 0ull;

    for (int c0 = 0; c0 < 96; c0 += 24) {
        __syncthreads();
        for (int i = tid; i < 24*32; i += 256) {
            int c = i >> 5, j = i & 31;
            float v = x[(b*96 + c0 + c)*LL + l0 + j];
            ((float2*)sXd)[c*32 + j] = make_float2(v, v);
        }
        for (int i = tid; i < 24*384; i += 256)
            sW[i] = W_in[c0*384 + i];
        __syncthreads();
#pragma unroll 4
        for (int cc = 0; cc < 24; cc++) {
            ull xd[4];
#pragma unroll
            for (int p = 0; p < 4; p++)
                xd[p] = ((const ull*)sXd)[cc*32 + jq*4 + p];
            const ull* wrow = (const ull*)(sW + cc*384);
#pragma unroll
            for (int k = 0; k < 6; k++) {
                ull wk = wrow[eg + 32*k];
#pragma unroll
                for (int p = 0; p < 4; p++)
                    acc[k][p] = f2fma(xd[p], wk, acc[k][p]);
            }
        }
    }
    int lbase = l0 + jq*4;
#pragma unroll
    for (int k = 0; k < 6; k++) {
        int e0 = 2*(eg + 32*k);
        float2 bb = *(const float2*)(b_in + e0);
#pragma unroll
        for (int p = 0; p < 4; p++) {
            float2 v = upk2(acc[k][p]);
            v.x += bb.x; v.y += bb.y;
            *(float2*)(g_xz + (size_t)(b*LL + lbase + p)*384 + e0) = v;
        }
    }
}

// ---------------- K2: depthwise 3x3 conv + bias + SiLU (4 px/thread) ----------------
__global__ void k2_conv(const float* __restrict__ w_dw, const float* __restrict__ b_dw) {
    int t = blockIdx.x*256 + threadIdx.x;
    int d = t % 192;
    int rem = t / 192;
    int w4 = rem % 24;
    int rem2 = rem / 24;
    int h = rem2 % HH;
    int b = rem2 / HH;
    int w0 = w4*4;

    float wt[9];
#pragma unroll
    for (int k = 0; k < 9; k++) wt[k] = w_dw[d*9 + k];
    float bias = b_dw[d];
    float acc[4] = {bias, bias, bias, bias};

#pragma unroll
    for (int kh = -1; kh <= 1; kh++) {
        int hh = h + kh;
        if (hh < 0 || hh >= HH) continue;
        float v[6];
#pragma unroll
        for (int c = 0; c < 6; c++) {
            int ww = w0 + c - 1;
            v[c] = (ww >= 0 && ww < WIMG)
                 ? g_xz[(size_t)(b*LL + hh*WIMG + ww)*384 + d] : 0.f;
        }
#pragma unroll
        for (int p = 0; p < 4; p++)
#pragma unroll
            for (int kw = 0; kw < 3; kw++)
                acc[p] = fmaf(v[p+kw], wt[(kh+1)*3 + kw], acc[p]);
    }
#pragma unroll
    for (int p = 0; p < 4; p++) {
        float a = acc[p];
        g_xc[(size_t)(b*LL + h*WIMG + w0 + p)*192 + d] = __fdividef(a, 1.f + __expf(-a));
    }
}

// ---------------- K3a: x_dbl partials (round-6, DO NOT TOUCH) ----------------
__global__ void k3a_xdbl() {
    __shared__ float sXf[32*132];
    __shared__ float sXb[32*132];
    __shared__ float sWf[32*40];
    __shared__ float sWb[32*40];
    int tid = threadIdx.x;
    int b  = blockIdx.z;
    int dh = blockIdx.y;
    int l0 = blockIdx.x*128;
    int d0 = dh*96;
    int pg = tid >> 3;
    int jg = tid & 7;

    float acc[4][5];
#pragma unroll
    for (int p = 0; p < 4; p++)
#pragma unroll
        for (int q = 0; q < 5; q++) acc[p][q] = 0.f;

    for (int ch = 0; ch < 3; ch++) {
        __syncthreads();
        int db = d0 + ch*32;
        for (int i = tid; i < 128*32; i += 256) {
            int pix = i >> 5, dd = i & 31;
            int l = l0 + pix;
            sXf[dd*132 + pix] = g_xc[(size_t)(b*LL + l)*192 + db + dd];
            sXb[dd*132 + pix] = g_xc[(size_t)(b*LL + (LL-1-l))*192 + db + dd];
        }
        for (int i = tid; i < 32*40; i += 256) {
            sWf[i] = g_Wf[db*40 + i];
            sWb[i] = g_Wb[db*40 + i];
        }
        __syncthreads();
#pragma unroll 4
        for (int dd = 0; dd < 32; dd++) {
            float4 xf4 = *(const float4*)(sXf + dd*132 + pg*4);
            float4 xb4 = *(const float4*)(sXb + dd*132 + pg*4);
            float xf[4] = {xf4.x, xf4.y, xf4.z, xf4.w};
            float xb[4] = {xb4.x, xb4.y, xb4.z, xb4.w};
            int wrow = dd*40 + jg*5;
            float wf[5], wb[5];
#pragma unroll
            for (int q = 0; q < 5; q++) { wf[q] = sWf[wrow+q]; wb[q] = sWb[wrow+q]; }
#pragma unroll
            for (int p = 0; p < 4; p++)
#pragma unroll
                for (int q = 0; q < 5; q++)
                    acc[p][q] += xf[p]*wf[q] + xb[p]*wb[q];
        }
    }
#pragma unroll
    for (int q = 0; q < 5; q++) {
        int j = jg*5 + q;
        if (j < 38) {
            int jm = (j < 6) ? j : j + 2;
#pragma unroll
            for (int p = 0; p < 4; p++) {
                int l = l0 + pg*4 + p;
                g_xdp[dh][(size_t)(b*LL + l)*40 + jm] = acc[p][q];
            }
        }
    }
}

__device__ __forceinline__ float xdp_sum(size_t idx) {
    return g_xdp[0][idx] + g_xdp[1][idx];
}

__device__ __forceinline__ bool a_structured(const float* An) {
    bool ok = true;
#pragma unroll
    for (int n = 1; n < NST; n++)
        ok = ok && (fabsf(An[n] - An[0]*(float)(n+1)) <= 1e-5f*(float)(n+1));
    return ok;
}

__device__ __forceinline__ float softplusf(float a) {
    return (a > 20.f) ? a : __logf(1.f + __expf(a));
}

// delta pre-activation via packed dot: 3 f2fma + horizontal add
__device__ __forceinline__ float delta_pre2(const float* row, const ull* wd2, float bd) {
    const ull* r2 = (const ull*)row;
    ull acc = f2mul(r2[0], wd2[0]);
    acc = f2fma(r2[1], wd2[1], acc);
    acc = f2fma(r2[2], wd2[2], acc);
    float2 a = upk2(acc);
    return a.x + a.y + bd;
}

// load 8 packed pairs (16 floats) via 4x LDS.128
__device__ __forceinline__ void ld8pairs(const float* p, ull* out) {
    ulonglong2 q0 = *(const ulonglong2*)(p);
    ulonglong2 q1 = *(const ulonglong2*)(p + 4);
    ulonglong2 q2 = *(const ulonglong2*)(p + 8);
    ulonglong2 q3 = *(const ulonglong2*)(p + 12);
    out[0] = q0.x; out[1] = q0.y;
    out[2] = q1.x; out[3] = q1.y;
    out[4] = q2.x; out[5] = q2.y;
    out[6] = q3.x; out[7] = q3.y;
}

// ---------------- K4a: scan pass A (direct u load, packed delta) ----------------
__global__ void __launch_bounds__(256, 4)
k4a_scanA(const float* __restrict__ Wd, const float* __restrict__ bde) {
    __shared__ __align__(16) float sXD[CLEN*40];
    int tid = threadIdx.x;
    int d4 = blockIdx.x*256 + tid;
    int c  = blockIdx.y;
    int b  = blockIdx.z;
    int l0 = c*CLEN;
    for (int i = tid; i < CLEN*40; i += 256)
        sXD[i] = xdp_sum((size_t)(b*LL + l0)*40 + i);
    __syncthreads();

    float wd[6];
#pragma unroll
    for (int r = 0; r < 6; r++) wd[r] = Wd[r*768 + d4];
    ull wd2[3] = {pk2(wd[0], wd[1]), pk2(wd[2], wd[3]), pk2(wd[4], wd[5])};
    float bd = bde[d4];

    float An[NST];
#pragma unroll
    for (int n = 0; n < NST; n++) An[n] = g_A[d4*NST + n];
    bool sA = a_structured(An);
    bool fwd = d4 < 384;
    int du = d4 % 192;
    float S = 0.f;

    if (sA) {
        ull h2[8];
#pragma unroll
        for (int k = 0; k < 8; k++) h2[k] = 0ull;
        const float* row = sXD;
        const float* up = g_xc + (size_t)(b*LL + (fwd ? l0 : (LL-1-l0)))*192 + du;
        long ustep = fwd ? 192 : -192;
        for (int i = 0; i < CLEN; i++, row += 40, up += ustep) {
            float a0 = delta_pre2(row, wd2, bd);
            float dl = softplusf(a0);
            S += dl;
            float u = *up;
            float s = dl*u;
            float e1 = __expf(dl*An[0]);
            ull av[8];
            av_ladder(e1, av);
            ull s2 = pk2(s, s);
            ull bb[8];
            ld8pairs(row + 8, bb);
#pragma unroll
            for (int k = 0; k < 8; k++)
                h2[k] = f2fma(av[k], h2[k], f2mul(s2, bb[k]));
        }
        size_t idx0 = ((size_t)(b*NCH + c)*768 + d4)*NST;
        float E = __expf(S*An[0]);
        float a = E;
        float4* H4 = (float4*)(g_chH + idx0);
        float4* P4 = (float4*)(g_chP + idx0);
#pragma unroll
        for (int k = 0; k < 4; k++) {
            float2 ha = upk2(h2[2*k]), hbv = upk2(h2[2*k+1]);
            H4[k] = make_float4(ha.x, ha.y, hbv.x, hbv.y);
            float p0 = a; a *= E;
            float p1 = a; a *= E;
            float p2s = a; a *= E;
            float p3 = a; a *= E;
            P4[k] = make_float4(p0, p1, p2s, p3);
        }
    } else {
        float h[NST];
#pragma unroll
        for (int n = 0; n < NST; n++) h[n] = 0.f;
        for (int i = 0; i < CLEN; i++) {
            const float* row = sXD + i*40;
            float a0 = bd;
#pragma unroll
            for (int r = 0; r < 6; r++) a0 = fmaf(row[r], wd[r], a0);
            float dl = softplusf(a0);
            S += dl;
            int l = l0 + i;
            int lu = fwd ? l : (LL-1-l);
            float u = g_xc[(size_t)(b*LL + lu)*192 + du];
            float s = dl*u;
            const float* bn = row + 8;
#pragma unroll
            for (int n = 0; n < NST; n++) {
                float a = __expf(dl*An[n]);
                h[n] = fmaf(a, h[n], s*bn[n]);
            }
        }
        float p[NST];
#pragma unroll
        for (int n = 0; n < NST; n++) p[n] = __expf(S*An[n]);
        size_t idx0 = ((size_t)(b*NCH + c)*768 + d4)*NST;
        float4* H4 = (float4*)(g_chH + idx0);
        float4* P4 = (float4*)(g_chP + idx0);
#pragma unroll
        for (int k = 0; k < 4; k++) {
            H4[k] = make_float4(h[4*k],h[4*k+1],h[4*k+2],h[4*k+3]);
            P4[k] = make_float4(p[4*k],p[4*k+1],p[4*k+2],p[4*k+3]);
        }
    }
}

// ---------------- K4b: prefix over chunks -> g_h0 (unroll 8) ----------------
__global__ void __launch_bounds__(256, 8)
k4b_prefix() {
    int g = blockIdx.x*256 + threadIdx.x;
    int n  = g & 15;
    int d4 = (g >> 4) % 768;
    int b  = g / (16*768);
    size_t base = ((size_t)b*NCH*768 + d4)*NST + n;
    float h = 0.f;
#pragma unroll 8
    for (int c = 0; c < NCH; c++) {
        size_t idx = base + (size_t)c*768*NST;
        float hc = g_chH[idx];
        float pp = g_chP[idx];
        g_h0[idx] = h;
        h = fmaf(pp, h, hc);
    }
}

// ---------------- K4c: scan pass C (pipelined u prefetch, emit y) ----------------
__global__ void __launch_bounds__(256, 4)
k4c_scanC(const float* __restrict__ Dp,
          const float* __restrict__ Wd, const float* __restrict__ bde) {
    __shared__ __align__(16) float sXD[CLEN*40];
    int tid = threadIdx.x;
    int d4 = blockIdx.x*256 + tid;
    int c  = blockIdx.y;
    int b  = blockIdx.z;
    int l0 = c*CLEN;
    for (int i = tid; i < CLEN*40; i += 256)
        sXD[i] = xdp_sum((size_t)(b*LL + l0)*40 + i);
    __syncthreads();

    float wd[6];
#pragma unroll
    for (int r = 0; r < 6; r++) wd[r] = Wd[r*768 + d4];
    ull wd2[3] = {pk2(wd[0], wd[1]), pk2(wd[2], wd[3]), pk2(wd[4], wd[5])};
    float bd = bde[d4];

    float An[NST];
#pragma unroll
    for (int n = 0; n < NST; n++) An[n] = g_A[d4*NST + n];
    bool sA = a_structured(An);
    bool fwd = d4 < 384;
    int du = d4 % 192;
    float dp = Dp[d4];

    size_t idx0 = ((size_t)(b*NCH + c)*768 + d4)*NST;
    const float4* H4 = (const float4*)(g_h0 + idx0);

    if (sA) {
        ull h2[8];
#pragma unroll
        for (int k = 0; k < 4; k++) {
            float4 hv = H4[k];
            h2[2*k]   = pk2(hv.x, hv.y);
            h2[2*k+1] = pk2(hv.z, hv.w);
        }
        const float* row = sXD;
        const float* up = g_xc + (size_t)(b*LL + (fwd ? l0 : (LL-1-l0)))*192 + du;
        long ustep = fwd ? 192 : -192;
        float* yp = g_y + (size_t)(b*LL + l0)*768 + d4;
        float u_cur = *up;
        for (int i = 0; i < CLEN; i++, row += 40, yp += 768) {
            up += ustep;
            float u_nxt = (i+1 < CLEN) ? *up : 0.f;
            float a0 = delta_pre2(row, wd2, bd);
            float dl = softplusf(a0);
            float s = dl*u_cur;
            float e1 = __expf(dl*An[0]);
            ull av[8];
            av_ladder(e1, av);
            ull s2 = pk2(s, s);
            ull bb[8], cc2[8];
            ld8pairs(row + 8, bb);
            ld8pairs(row + 24, cc2);
            ull y2 = 0ull;
#pragma unroll
            for (int k = 0; k < 8; k++) {
                h2[k] = f2fma(av[k], h2[k], f2mul(s2, bb[k]));
                y2 = f2fma(h2[k], cc2[k], y2);
            }
            float2 yy = upk2(y2);
            *yp = dp*u_cur + yy.x + yy.y;
            u_cur = u_nxt;
        }
    } else {
        float h[NST];
#pragma unroll
        for (int k = 0; k < 4; k++) {
            float4 hv = H4[k];
            h[4*k] = hv.x; h[4*k+1] = hv.y; h[4*k+2] = hv.z; h[4*k+3] = hv.w;
        }
        for (int i = 0; i < CLEN; i++) {
            const float* row = sXD + i*40;
            float a0 = bd;
#pragma unroll
            for (int r = 0; r < 6; r++) a0 = fmaf(row[r], wd[r], a0);
            float dl = softplusf(a0);
            int l = l0 + i;
            int lu = fwd ? l : (LL-1-l);
            float u = g_xc[(size_t)(b*LL + lu)*192 + du];
            float s = dl*u;
            const float* bn = row + 8;
            const float* cn = row + 24;
            float y = dp*u;
#pragma unroll
            for (int n = 0; n < NST; n++) {
                float a = __expf(dl*An[n]);
                h[n] = fmaf(a, h[n], s*bn[n]);
                y = fmaf(h[n], cn[n], y);
            }
            g_y[(size_t)(b*LL + l)*768 + d4] = y;
        }
    }
}

// ---------------- K5a: combine + LN + gate, 32-px tile, coalesced writes ----------------
__global__ void k5a_gate(const float* __restrict__ ln_g, const float* __restrict__ ln_b) {
    __shared__ float sT[32][193];
    int tid = threadIdx.x;
    int warp = tid >> 5, lane = tid & 31;
    int b  = blockIdx.y;
    int p0 = blockIdx.x*32;

    float lg[6], lb[6];
#pragma unroll
    for (int k = 0; k < 6; k++) {
        int ch = lane + 32*k;
        lg[k] = ln_g[ch];
        lb[k] = ln_b[ch];
    }

    for (int pi = warp; pi < 32; pi += 8) {
        int p  = p0 + pi;
        int pf = LL - 1 - p;
        const float* yr  = g_y + (size_t)(b*LL + p)*768;
        const float* yrf = g_y + (size_t)(b*LL + pf)*768;

        float v[6];
        float s1 = 0.f, s2 = 0.f;
#pragma unroll
        for (int k = 0; k < 6; k++) {
            int ch = lane + 32*k;
            float vv = yr[ch] + yr[192+ch] + yrf[384+ch] + yrf[576+ch];
            v[k] = vv;
            s1 += vv; s2 += vv*vv;
        }
#pragma unroll
        for (int off = 16; off >= 1; off >>= 1) {
            s1 += __shfl_xor_sync(0xffffffffu, s1, off);
            s2 += __shfl_xor_sync(0xffffffffu, s2, off);
        }
        float mu = s1 * (1.f/192.f);
        float var = s2 * (1.f/192.f) - mu*mu;
        float rstd = rsqrtf(var + 1e-5f);

        const float* zrow = g_xz + (size_t)(b*LL + p)*384 + 192;
#pragma unroll
        for (int k = 0; k < 6; k++) {
            int ch = lane + 32*k;
            float yn = (v[k] - mu)*rstd*lg[k] + lb[k];
            float z  = zrow[ch];
            sT[pi][ch] = yn * __fdividef(z, 1.f + __expf(-z));
        }
    }
    __syncthreads();
    for (int i = tid; i < 192*32; i += 256) {
        int ch = i >> 5, pp = i & 31;
        g_gT[(size_t)(b*192 + ch)*LL + p0 + pp] = sT[pp][ch];
    }
}

// ---------------- K5b: out GEMM (192 -> 96), f32x2 ----------------
__global__ void __launch_bounds__(256, 4)
k5b_out(const float* __restrict__ W_out, float* __restrict__ out) {
    __shared__ float sG [32*68];
    __shared__ float sWd[32*192];
    int tid = threadIdx.x;
    int b  = blockIdx.y;
    int l0 = blockIdx.x*64;
    int eg = tid & 31;
    int jq = tid >> 5;
    ull acc[3][4];
#pragma unroll
    for (int e = 0; e < 3; e++)
#pragma unroll
        for (int p = 0; p < 4; p++) acc[e][p] = 0ull;

    for (int k0 = 0; k0 < 192; k0 += 32) {
        __syncthreads();
        for (int i = tid; i < 32*64; i += 256) {
            int dd = i >> 6, pix = i & 63;
            sG[dd*68 + pix] = g_gT[(size_t)(b*192 + k0 + dd)*LL + l0 + pix];
        }
        for (int i = tid; i < 32*96; i += 256) {
            int dd = i/96, cc = i%96;
            float v = W_out[k0*96 + i];
            ((float2*)sWd)[dd*96 + cc] = make_float2(v, v);
        }
        __syncthreads();
#pragma unroll 4
        for (int dd = 0; dd < 32; dd++) {
            ulonglong2 xa = *(const ulonglong2*)(sG + dd*68 + jq*8);
            ulonglong2 xb = *(const ulonglong2*)(sG + dd*68 + jq*8 + 4);
            const ull* wr = (const ull*)sWd + dd*96;
#pragma unroll
            for (int e = 0; e < 3; e++) {
                ull w = wr[e*32 + eg];
                acc[e][0] = f2fma(xa.x, w, acc[e][0]);
                acc[e][1] = f2fma(xa.y, w, acc[e][1]);
                acc[e][2] = f2fma(xb.x, w, acc[e][2]);
                acc[e][3] = f2fma(xb.y, w, acc[e][3]);
            }
        }
    }
#pragma unroll
    for (int e = 0; e < 3; e++) {
        int cc = e*32 + eg;
        float2 v0 = upk2(acc[e][0]), v1 = upk2(acc[e][1]);
        float2 v2 = upk2(acc[e][2]), v3 = upk2(acc[e][3]);
        float* op = out + (size_t)(b*96 + cc)*LL + l0 + jq*8;
        *(float4*)(op)     = make_float4(v0.x, v0.y, v1.x, v1.y);
        *(float4*)(op + 4) = make_float4(v2.x, v2.y, v3.x, v3.y);
    }
}

// ---------------- launch ----------------
extern "C" void kernel_launch(void* const* d_in, const int* in_sizes, int n_in,
                              void* d_out, int out_size) {
    const float* x       = (const float*)d_in[0];
    const float* W_in    = (const float*)d_in[1];
    const float* b_in    = (const float*)d_in[2];
    const float* w_dw    = (const float*)d_in[3];
    const float* b_dw    = (const float*)d_in[4];
    const float* A_log   = (const float*)d_in[5];
    const float* Dp      = (const float*)d_in[6];
    const float* W_x     = (const float*)d_in[7];
    const float* W_delta = (const float*)d_in[8];
    const float* b_delta = (const float*)d_in[9];
    const float* ln_g    = (const float*)d_in[10];
    const float* ln_b    = (const float*)d_in[11];
    const float* W_out   = (const float*)d_in[12];
    float* out = (float*)d_out;

    k1_inproj<<<dim3(LL/32, BB), 256>>>(x, W_in, b_in, A_log, W_x);
    k2_conv<<<(BB*HH*24*192)/256, 256>>>(w_dw, b_dw);
    k3a_xdbl<<<dim3(72, 2, BB), 256>>>();
    k4a_scanA<<<dim3(3, NCH, BB), 256>>>(W_delta, b_delta);
    k4b_prefix<<<(BB*768*16)/256, 256>>>();
    k4c_scanC<<<dim3(3, NCH, BB), 256>>>(Dp, W_delta, b_delta);
    k5a_gate<<<dim3(LL/32, BB), 256>>>(ln_g, ln_b);
    k5b_out<<<dim3(LL/64, BB), 256>>>(W_out, out);
}

// round 17
// speedup vs baseline: 1.0657x; 1.0133x over previous
#include <cuda_runtime.h>
#include <cuda_bf16.h>
#include <math.h>

#define BB   2
#define LL   9216
#define HH   96
#define WIMG 96
#define D2C  192
#define D4C  768
#define NST  16
#define NCH  96
#define CLEN 96

typedef unsigned long long ull;

// ---------------- scratch (device globals; no allocation) ----------------
__device__ float g_xz   [BB*LL*384];
__device__ float g_xc   [BB*LL*D2C];
__device__ float g_xdp  [2][BB*LL*40];
__device__ float g_y    [BB*LL*D4C];
__device__ float g_gT   [BB*D2C*LL];
__device__ float g_chH  [BB*NCH*D4C*NST];
__device__ float g_chP  [BB*NCH*D4C*NST];
__device__ float g_h0   [BB*NCH*D4C*NST];
__device__ float g_A    [D4C*NST];
__device__ float g_Wf   [D2C*40];
__device__ float g_Wb   [D2C*40];

// ---------------- packed f32x2 helpers ----------------
__device__ __forceinline__ ull pk2(float lo, float hi) {
    ull r;
    asm("mov.b64 %0, {%1, %2};" : "=l"(r) : "f"(lo), "f"(hi));
    return r;
}
__device__ __forceinline__ float2 upk2(ull v) {
    float2 r;
    asm("mov.b64 {%0, %1}, %2;" : "=f"(r.x), "=f"(r.y) : "l"(v));
    return r;
}
__device__ __forceinline__ ull f2mul(ull a, ull b) {
    ull d;
    asm("mul.rn.f32x2 %0, %1, %2;" : "=l"(d) : "l"(a), "l"(b));
    return d;
}
__device__ __forceinline__ ull f2fma(ull a, ull b, ull c) {
    ull d;
    asm("fma.rn.f32x2 %0, %1, %2, %3;" : "=l"(d) : "l"(a), "l"(b), "l"(c));
    return d;
}

// log-depth ladder: av[k] = (e1^(2k+1), e1^(2k+2)), k=0..7
__device__ __forceinline__ void av_ladder(float e1, ull* av) {
    float e2 = e1*e1;
    float e4 = e2*e2;
    float e8 = e4*e4;
    ull p2 = pk2(e2, e2), p4 = pk2(e4, e4), p8 = pk2(e8, e8);
    av[0] = pk2(e1, e2);
    av[1] = f2mul(av[0], p2);
    av[2] = f2mul(av[0], p4);
    av[3] = f2mul(av[1], p4);
    av[4] = f2mul(av[0], p8);
    av[5] = f2mul(av[1], p8);
    av[6] = f2mul(av[2], p8);
    av[7] = f2mul(av[3], p8);
}

// fused dl = softplus(a0), e1 = exp(-dl) = 1/(1+e^{a0});  requires A0 == -1
__device__ __forceinline__ void dl_e1(float a0, float& dl, float& e1) {
    float t = __expf(fminf(a0, 80.f));
    float w = 1.f + t;
    float r;
    asm("rcp.approx.f32 %0, %1;" : "=f"(r) : "f"(w));
    float lg = __logf(w);
    dl = (a0 > 80.f) ? a0 : lg;
    e1 = r;
}

// ---------------- K1: in-projection GEMM + folded prep ----------------
__global__ void k1_inproj(const float* __restrict__ x,
                          const float* __restrict__ W_in,
                          const float* __restrict__ b_in,
                          const float* __restrict__ A_log,
                          const float* __restrict__ W_x) {
    __shared__ float sXd[24*64];
    __shared__ float sW [24*384];
    int tid = threadIdx.x;
    int b  = blockIdx.y;
    int l0 = blockIdx.x*32;

    if (b == 0) {
        int i = blockIdx.x*256 + tid;
        if (i < D4C*NST) g_A[i] = -expf(A_log[i]);
        if (i < D2C*40) {
            int d = i/40, j = i%40;
            float vf = 0.f, vb = 0.f;
            if (j < 38) {
                vf = W_x[d*38+j]       + W_x[(d+192)*38+j];
                vb = W_x[(d+384)*38+j] + W_x[(d+576)*38+j];
            }
            g_Wf[i] = vf;
            g_Wb[i] = vb;
        }
    }

    int eg = tid & 31;
    int jq = tid >> 5;
    ull acc[6][4];
#pragma unroll
    for (int k = 0; k < 6; k++)
#pragma unroll
        for (int p = 0; p < 4; p++) acc[k][p] = 0ull;

    for (int c0 = 0; c0 < 96; c0 += 24) {
        __syncthreads();
        for (int i = tid; i < 24*32; i += 256) {
            int c = i >> 5, j = i & 31;
            float v = x[(b*96 + c0 + c)*LL + l0 + j];
            ((float2*)sXd)[c*32 + j] = make_float2(v, v);
        }
        for (int i = tid; i < 24*384; i += 256)
            sW[i] = W_in[c0*384 + i];
        __syncthreads();
#pragma unroll 4
        for (int cc = 0; cc < 24; cc++) {
            ull xd[4];
#pragma unroll
            for (int p = 0; p < 4; p++)
                xd[p] = ((const ull*)sXd)[cc*32 + jq*4 + p];
            const ull* wrow = (const ull*)(sW + cc*384);
#pragma unroll
            for (int k = 0; k < 6; k++) {
                ull wk = wrow[eg + 32*k];
#pragma unroll
                for (int p = 0; p < 4; p++)
                    acc[k][p] = f2fma(xd[p], wk, acc[k][p]);
            }
        }
    }
    int lbase = l0 + jq*4;
#pragma unroll
    for (int k = 0; k < 6; k++) {
        int e0 = 2*(eg + 32*k);
        float2 bb = *(const float2*)(b_in + e0);
#pragma unroll
        for (int p = 0; p < 4; p++) {
            float2 v = upk2(acc[k][p]);
            v.x += bb.x; v.y += bb.y;
            *(float2*)(g_xz + (size_t)(b*LL + lbase + p)*384 + e0) = v;
        }
    }
}

// ---------------- K2: depthwise 3x3 conv + bias + SiLU (4 px/thread) ----------------
__global__ void k2_conv(const float* __restrict__ w_dw, const float* __restrict__ b_dw) {
    int t = blockIdx.x*256 + threadIdx.x;
    int d = t % 192;
    int rem = t / 192;
    int w4 = rem % 24;
    int rem2 = rem / 24;
    int h = rem2 % HH;
    int b = rem2 / HH;
    int w0 = w4*4;

    float wt[9];
#pragma unroll
    for (int k = 0; k < 9; k++) wt[k] = w_dw[d*9 + k];
    float bias = b_dw[d];
    float acc[4] = {bias, bias, bias, bias};

#pragma unroll
    for (int kh = -1; kh <= 1; kh++) {
        int hh = h + kh;
        if (hh < 0 || hh >= HH) continue;
        float v[6];
#pragma unroll
        for (int c = 0; c < 6; c++) {
            int ww = w0 + c - 1;
            v[c] = (ww >= 0 && ww < WIMG)
                 ? g_xz[(size_t)(b*LL + hh*WIMG + ww)*384 + d] : 0.f;
        }
#pragma unroll
        for (int p = 0; p < 4; p++)
#pragma unroll
            for (int kw = 0; kw < 3; kw++)
                acc[p] = fmaf(v[p+kw], wt[(kh+1)*3 + kw], acc[p]);
    }
#pragma unroll
    for (int p = 0; p < 4; p++) {
        float a = acc[p];
        g_xc[(size_t)(b*LL + h*WIMG + w0 + p)*192 + d] = __fdividef(a, 1.f + __expf(-a));
    }
}

// ---------------- K3a: x_dbl partials (round-6, DO NOT TOUCH) ----------------
__global__ void k3a_xdbl() {
    __shared__ float sXf[32*132];
    __shared__ float sXb[32*132];
    __shared__ float sWf[32*40];
    __shared__ float sWb[32*40];
    int tid = threadIdx.x;
    int b  = blockIdx.z;
    int dh = blockIdx.y;
    int l0 = blockIdx.x*128;
    int d0 = dh*96;
    int pg = tid >> 3;
    int jg = tid & 7;

    float acc[4][5];
#pragma unroll
    for (int p = 0; p < 4; p++)
#pragma unroll
        for (int q = 0; q < 5; q++) acc[p][q] = 0.f;

    for (int ch = 0; ch < 3; ch++) {
        __syncthreads();
        int db = d0 + ch*32;
        for (int i = tid; i < 128*32; i += 256) {
            int pix = i >> 5, dd = i & 31;
            int l = l0 + pix;
            sXf[dd*132 + pix] = g_xc[(size_t)(b*LL + l)*192 + db + dd];
            sXb[dd*132 + pix] = g_xc[(size_t)(b*LL + (LL-1-l))*192 + db + dd];
        }
        for (int i = tid; i < 32*40; i += 256) {
            sWf[i] = g_Wf[db*40 + i];
            sWb[i] = g_Wb[db*40 + i];
        }
        __syncthreads();
#pragma unroll 4
        for (int dd = 0; dd < 32; dd++) {
            float4 xf4 = *(const float4*)(sXf + dd*132 + pg*4);
            float4 xb4 = *(const float4*)(sXb + dd*132 + pg*4);
            float xf[4] = {xf4.x, xf4.y, xf4.z, xf4.w};
            float xb[4] = {xb4.x, xb4.y, xb4.z, xb4.w};
            int wrow = dd*40 + jg*5;
            float wf[5], wb[5];
#pragma unroll
            for (int q = 0; q < 5; q++) { wf[q] = sWf[wrow+q]; wb[q] = sWb[wrow+q]; }
#pragma unroll
            for (int p = 0; p < 4; p++)
#pragma unroll
                for (int q = 0; q < 5; q++)
                    acc[p][q] += xf[p]*wf[q] + xb[p]*wb[q];
        }
    }
#pragma unroll
    for (int q = 0; q < 5; q++) {
        int j = jg*5 + q;
        if (j < 38) {
            int jm = (j < 6) ? j : j + 2;
#pragma unroll
            for (int p = 0; p < 4; p++) {
                int l = l0 + pg*4 + p;
                g_xdp[dh][(size_t)(b*LL + l)*40 + jm] = acc[p][q];
            }
        }
    }
}

__device__ __forceinline__ float xdp_sum(size_t idx) {
    return g_xdp[0][idx] + g_xdp[1][idx];
}

// structured AND A0 == -1 (true for this model)
__device__ __forceinline__ bool a_structured(const float* An) {
    bool ok = (fabsf(An[0] + 1.f) <= 1e-6f);
#pragma unroll
    for (int n = 1; n < NST; n++)
        ok = ok && (fabsf(An[n] - An[0]*(float)(n+1)) <= 1e-5f*(float)(n+1));
    return ok;
}

__device__ __forceinline__ float softplusf(float a) {
    return (a > 20.f) ? a : __logf(1.f + __expf(a));
}

// delta pre-activation via packed dot: 3 f2fma + horizontal add
__device__ __forceinline__ float delta_pre2(const float* row, const ull* wd2, float bd) {
    const ull* r2 = (const ull*)row;
    ull acc = f2mul(r2[0], wd2[0]);
    acc = f2fma(r2[1], wd2[1], acc);
    acc = f2fma(r2[2], wd2[2], acc);
    float2 a = upk2(acc);
    return a.x + a.y + bd;
}

// load 8 packed pairs (16 floats) via 4x LDS.128
__device__ __forceinline__ void ld8pairs(const float* p, ull* out) {
    ulonglong2 q0 = *(const ulonglong2*)(p);
    ulonglong2 q1 = *(const ulonglong2*)(p + 4);
    ulonglong2 q2 = *(const ulonglong2*)(p + 8);
    ulonglong2 q3 = *(const ulonglong2*)(p + 12);
    out[0] = q0.x; out[1] = q0.y;
    out[2] = q1.x; out[3] = q1.y;
    out[4] = q2.x; out[5] = q2.y;
    out[6] = q3.x; out[7] = q3.y;
}

// ---------------- K4a: scan pass A (direct u load, fused dl/e1) ----------------
__global__ void __launch_bounds__(256, 4)
k4a_scanA(const float* __restrict__ Wd, const float* __restrict__ bde) {
    __shared__ __align__(16) float sXD[CLEN*40];
    int tid = threadIdx.x;
    int d4 = blockIdx.x*256 + tid;
    int c  = blockIdx.y;
    int b  = blockIdx.z;
    int l0 = c*CLEN;
    for (int i = tid; i < CLEN*40; i += 256)
        sXD[i] = xdp_sum((size_t)(b*LL + l0)*40 + i);
    __syncthreads();

    float wd[6];
#pragma unroll
    for (int r = 0; r < 6; r++) wd[r] = Wd[r*768 + d4];
    ull wd2[3] = {pk2(wd[0], wd[1]), pk2(wd[2], wd[3]), pk2(wd[4], wd[5])};
    float bd = bde[d4];

    float An[NST];
#pragma unroll
    for (int n = 0; n < NST; n++) An[n] = g_A[d4*NST + n];
    bool sA = a_structured(An);
    bool fwd = d4 < 384;
    int du = d4 % 192;
    float S = 0.f;

    if (sA) {
        ull h2[8];
#pragma unroll
        for (int k = 0; k < 8; k++) h2[k] = 0ull;
        const float* row = sXD;
        const float* up = g_xc + (size_t)(b*LL + (fwd ? l0 : (LL-1-l0)))*192 + du;
        long ustep = fwd ? 192 : -192;
        for (int i = 0; i < CLEN; i++, row += 40, up += ustep) {
            float a0 = delta_pre2(row, wd2, bd);
            float dl, e1;
            dl_e1(a0, dl, e1);
            S += dl;
            float u = *up;
            float s = dl*u;
            ull av[8];
            av_ladder(e1, av);
            ull s2 = pk2(s, s);
            ull bb[8];
            ld8pairs(row + 8, bb);
#pragma unroll
            for (int k = 0; k < 8; k++)
                h2[k] = f2fma(av[k], h2[k], f2mul(s2, bb[k]));
        }
        size_t idx0 = ((size_t)(b*NCH + c)*768 + d4)*NST;
        float E = __expf(-S);        // A0 == -1
        float a = E;
        float4* H4 = (float4*)(g_chH + idx0);
        float4* P4 = (float4*)(g_chP + idx0);
#pragma unroll
        for (int k = 0; k < 4; k++) {
            float2 ha = upk2(h2[2*k]), hbv = upk2(h2[2*k+1]);
            H4[k] = make_float4(ha.x, ha.y, hbv.x, hbv.y);
            float p0 = a; a *= E;
            float p1 = a; a *= E;
            float p2s = a; a *= E;
            float p3 = a; a *= E;
            P4[k] = make_float4(p0, p1, p2s, p3);
        }
    } else {
        float h[NST];
#pragma unroll
        for (int n = 0; n < NST; n++) h[n] = 0.f;
        for (int i = 0; i < CLEN; i++) {
            const float* row = sXD + i*40;
            float a0 = bd;
#pragma unroll
            for (int r = 0; r < 6; r++) a0 = fmaf(row[r], wd[r], a0);
            float dl = softplusf(a0);
            S += dl;
            int l = l0 + i;
            int lu = fwd ? l : (LL-1-l);
            float u = g_xc[(size_t)(b*LL + lu)*192 + du];
            float s = dl*u;
            const float* bn = row + 8;
#pragma unroll
            for (int n = 0; n < NST; n++) {
                float a = __expf(dl*An[n]);
                h[n] = fmaf(a, h[n], s*bn[n]);
            }
        }
        float p[NST];
#pragma unroll
        for (int n = 0; n < NST; n++) p[n] = __expf(S*An[n]);
        size_t idx0 = ((size_t)(b*NCH + c)*768 + d4)*NST;
        float4* H4 = (float4*)(g_chH + idx0);
        float4* P4 = (float4*)(g_chP + idx0);
#pragma unroll
        for (int k = 0; k < 4; k++) {
            H4[k] = make_float4(h[4*k],h[4*k+1],h[4*k+2],h[4*k+3]);
            P4[k] = make_float4(p[4*k],p[4*k+1],p[4*k+2],p[4*k+3]);
        }
    }
}

// ---------------- K4b: prefix over chunks -> g_h0 (unroll 8) ----------------
__global__ void __launch_bounds__(256, 8)
k4b_prefix() {
    int g = blockIdx.x*256 + threadIdx.x;
    int n  = g & 15;
    int d4 = (g >> 4) % 768;
    int b  = g / (16*768);
    size_t base = ((size_t)b*NCH*768 + d4)*NST + n;
    float h = 0.f;
#pragma unroll 8
    for (int c = 0; c < NCH; c++) {
        size_t idx = base + (size_t)c*768*NST;
        float hc = g_chH[idx];
        float pp = g_chP[idx];
        g_h0[idx] = h;
        h = fmaf(pp, h, hc);
    }
}

// ---------------- K4c: scan pass C (pipelined u prefetch, fused dl/e1, emit y) ----------------
__global__ void __launch_bounds__(256, 4)
k4c_scanC(const float* __restrict__ Dp,
          const float* __restrict__ Wd, const float* __restrict__ bde) {
    __shared__ __align__(16) float sXD[CLEN*40];
    int tid = threadIdx.x;
    int d4 = blockIdx.x*256 + tid;
    int c  = blockIdx.y;
    int b  = blockIdx.z;
    int l0 = c*CLEN;
    for (int i = tid; i < CLEN*40; i += 256)
        sXD[i] = xdp_sum((size_t)(b*LL + l0)*40 + i);
    __syncthreads();

    float wd[6];
#pragma unroll
    for (int r = 0; r < 6; r++) wd[r] = Wd[r*768 + d4];
    ull wd2[3] = {pk2(wd[0], wd[1]), pk2(wd[2], wd[3]), pk2(wd[4], wd[5])};
    float bd = bde[d4];

    float An[NST];
#pragma unroll
    for (int n = 0; n < NST; n++) An[n] = g_A[d4*NST + n];
    bool sA = a_structured(An);
    bool fwd = d4 < 384;
    int du = d4 % 192;
    float dp = Dp[d4];

    size_t idx0 = ((size_t)(b*NCH + c)*768 + d4)*NST;
    const float4* H4 = (const float4*)(g_h0 + idx0);

    if (sA) {
        ull h2[8];
#pragma unroll
        for (int k = 0; k < 4; k++) {
            float4 hv = H4[k];
            h2[2*k]   = pk2(hv.x, hv.y);
            h2[2*k+1] = pk2(hv.z, hv.w);
        }
        const float* row = sXD;
        const float* up = g_xc + (size_t)(b*LL + (fwd ? l0 : (LL-1-l0)))*192 + du;
        long ustep = fwd ? 192 : -192;
        float* yp = g_y + (size_t)(b*LL + l0)*768 + d4;
        float u_cur = *up;
        for (int i = 0; i < CLEN; i++, row += 40, yp += 768) {
            up += ustep;
            float u_nxt = (i+1 < CLEN) ? *up : 0.f;
            float a0 = delta_pre2(row, wd2, bd);
            float dl, e1;
            dl_e1(a0, dl, e1);
            float s = dl*u_cur;
            ull av[8];
            av_ladder(e1, av);
            ull s2 = pk2(s, s);
            ull bb[8], cc2[8];
            ld8pairs(row + 8, bb);
            ld8pairs(row + 24, cc2);
            ull y2 = 0ull;
#pragma unroll
            for (int k = 0; k < 8; k++) {
                h2[k] = f2fma(av[k], h2[k], f2mul(s2, bb[k]));
                y2 = f2fma(h2[k], cc2[k], y2);
            }
            float2 yy = upk2(y2);
            *yp = dp*u_cur + yy.x + yy.y;
            u_cur = u_nxt;
        }
    } else {
        float h[NST];
#pragma unroll
        for (int k = 0; k < 4; k++) {
            float4 hv = H4[k];
            h[4*k] = hv.x; h[4*k+1] = hv.y; h[4*k+2] = hv.z; h[4*k+3] = hv.w;
        }
        for (int i = 0; i < CLEN; i++) {
            const float* row = sXD + i*40;
            float a0 = bd;
#pragma unroll
            for (int r = 0; r < 6; r++) a0 = fmaf(row[r], wd[r], a0);
            float dl = softplusf(a0);
            int l = l0 + i;
            int lu = fwd ? l : (LL-1-l);
            float u = g_xc[(size_t)(b*LL + lu)*192 + du];
            float s = dl*u;
            const float* bn = row + 8;
            const float* cn = row + 24;
            float y = dp*u;
#pragma unroll
            for (int n = 0; n < NST; n++) {
                float a = __expf(dl*An[n]);
                h[n] = fmaf(a, h[n], s*bn[n]);
                y = fmaf(h[n], cn[n], y);
            }
            g_y[(size_t)(b*LL + l)*768 + d4] = y;
        }
    }
}

// ---------------- K5a: combine + LN + gate, 32-px tile, coalesced writes ----------------
__global__ void k5a_gate(const float* __restrict__ ln_g, const float* __restrict__ ln_b) {
    __shared__ float sT[32][193];
    int tid = threadIdx.x;
    int warp = tid >> 5, lane = tid & 31;
    int b  = blockIdx.y;
    int p0 = blockIdx.x*32;

    float lg[6], lb[6];
#pragma unroll
    for (int k = 0; k < 6; k++) {
        int ch = lane + 32*k;
        lg[k] = ln_g[ch];
        lb[k] = ln_b[ch];
    }

    for (int pi = warp; pi < 32; pi += 8) {
        int p  = p0 + pi;
        int pf = LL - 1 - p;
        const float* yr  = g_y + (size_t)(b*LL + p)*768;
        const float* yrf = g_y + (size_t)(b*LL + pf)*768;

        float v[6];
        float s1 = 0.f, s2 = 0.f;
#pragma unroll
        for (int k = 0; k < 6; k++) {
            int ch = lane + 32*k;
            float vv = yr[ch] + yr[192+ch] + yrf[384+ch] + yrf[576+ch];
            v[k] = vv;
            s1 += vv; s2 += vv*vv;
        }
#pragma unroll
        for (int off = 16; off >= 1; off >>= 1) {
            s1 += __shfl_xor_sync(0xffffffffu, s1, off);
            s2 += __shfl_xor_sync(0xffffffffu, s2, off);
        }
        float mu = s1 * (1.f/192.f);
        float var = s2 * (1.f/192.f) - mu*mu;
        float rstd = rsqrtf(var + 1e-5f);

        const float* zrow = g_xz + (size_t)(b*LL + p)*384 + 192;
#pragma unroll
        for (int k = 0; k < 6; k++) {
            int ch = lane + 32*k;
            float yn = (v[k] - mu)*rstd*lg[k] + lb[k];
            float z  = zrow[ch];
            sT[pi][ch] = yn * __fdividef(z, 1.f + __expf(-z));
        }
    }
    __syncthreads();
    for (int i = tid; i < 192*32; i += 256) {
        int ch = i >> 5, pp = i & 31;
        g_gT[(size_t)(b*192 + ch)*LL + p0 + pp] = sT[pp][ch];
    }
}

// ---------------- K5b: out GEMM (192 -> 96), f32x2 ----------------
__global__ void __launch_bounds__(256, 4)
k5b_out(const float* __restrict__ W_out, float* __restrict__ out) {
    __shared__ float sG [32*68];
    __shared__ float sWd[32*192];
    int tid = threadIdx.x;
    int b  = blockIdx.y;
    int l0 = blockIdx.x*64;
    int eg = tid & 31;
    int jq = tid >> 5;
    ull acc[3][4];
#pragma unroll
    for (int e = 0; e < 3; e++)
#pragma unroll
        for (int p = 0; p < 4; p++) acc[e][p] = 0ull;

    for (int k0 = 0; k0 < 192; k0 += 32) {
        __syncthreads();
        for (int i = tid; i < 32*64; i += 256) {
            int dd = i >> 6, pix = i & 63;
            sG[dd*68 + pix] = g_gT[(size_t)(b*192 + k0 + dd)*LL + l0 + pix];
        }
        for (int i = tid; i < 32*96; i += 256) {
            int dd = i/96, cc = i%96;
            float v = W_out[k0*96 + i];
            ((float2*)sWd)[dd*96 + cc] = make_float2(v, v);
        }
        __syncthreads();
#pragma unroll 4
        for (int dd = 0; dd < 32; dd++) {
            ulonglong2 xa = *(const ulonglong2*)(sG + dd*68 + jq*8);
            ulonglong2 xb = *(const ulonglong2*)(sG + dd*68 + jq*8 + 4);
            const ull* wr = (const ull*)sWd + dd*96;
#pragma unroll
            for (int e = 0; e < 3; e++) {
                ull w = wr[e*32 + eg];
                acc[e][0] = f2fma(xa.x, w, acc[e][0]);
                acc[e][1] = f2fma(xa.y, w, acc[e][1]);
                acc[e][2] = f2fma(xb.x, w, acc[e][2]);
                acc[e][3] = f2fma(xb.y, w, acc[e][3]);
            }
        }
    }
#pragma unroll
    for (int e = 0; e < 3; e++) {
        int cc = e*32 + eg;
        float2 v0 = upk2(acc[e][0]), v1 = upk2(acc[e][1]);
        float2 v2 = upk2(acc[e][2]), v3 = upk2(acc[e][3]);
        float* op = out + (size_t)(b*96 + cc)*LL + l0 + jq*8;
        *(float4*)(op)     = make_float4(v0.x, v0.y, v1.x, v1.y);
        *(float4*)(op + 4) = make_float4(v2.x, v2.y, v3.x, v3.y);
    }
}

// ---------------- launch ----------------
extern "C" void kernel_launch(void* const* d_in, const int* in_sizes, int n_in,
                              void* d_out, int out_size) {
    const float* x       = (const float*)d_in[0];
    const float* W_in    = (const float*)d_in[1];
    const float* b_in    = (const float*)d_in[2];
    const float* w_dw    = (const float*)d_in[3];
    const float* b_dw    = (const float*)d_in[4];
    const float* A_log   = (const float*)d_in[5];
    const float* Dp      = (const float*)d_in[6];
    const float* W_x     = (const float*)d_in[7];
    const float* W_delta = (const float*)d_in[8];
    const float* b_delta = (const float*)d_in[9];
    const float* ln_g    = (const float*)d_in[10];
    const float* ln_b    = (const float*)d_in[11];
    const float* W_out   = (const float*)d_in[12];
    float* out = (float*)d_out;

    k1_inproj<<<dim3(LL/32, BB), 256>>>(x, W_in, b_in, A_log, W_x);
    k2_conv<<<(BB*HH*24*192)/256, 256>>>(w_dw, b_dw);
    k3a_xdbl<<<dim3(72, 2, BB), 256>>>();
    k4a_scanA<<<dim3(3, NCH, BB), 256>>>(W_delta, b_delta);
    k4b_prefix<<<(BB*768*16)/256, 256>>>();
    k4c_scanC<<<dim3(3, NCH, BB), 256>>>(Dp, W_delta, b_delta);
    k5a_gate<<<dim3(LL/32, BB), 256>>>(ln_g, ln_b);
    k5b_out<<<dim3(LL/64, BB), 256>>>(W_out, out);
}